// round 1
// baseline (speedup 1.0000x reference)
#include <cuda_runtime.h>

// ---------------- problem constants ----------------
constexpr int NB    = 8;      // meta-batch (tasks)
constexpr int NT    = 5;      // inner steps
constexpr int NL    = 16;     // test examples per task
constexpr int NTEST = NB * NL;          // 128
constexpr int NCLS  = 100;
constexpr int FEAT  = 4096;
constexpr int CHW   = 3 * 64 * 64;

// per-example parameter block offsets (concatenated)
constexpr int OFF_W0 = 0;        constexpr int SZ_W0 = 32 * 3 * 9;     // 864
constexpr int OFF_B0 = 864;      constexpr int SZ_B0 = 32;
constexpr int OFF_W1 = 896;      constexpr int SZ_W1 = 64 * 32 * 9;    // 18432
constexpr int OFF_B1 = 19328;    constexpr int SZ_B1 = 64;
constexpr int OFF_W2 = 19392;    constexpr int SZ_W2 = 128 * 64 * 9;   // 73728
constexpr int OFF_B2 = 93120;    constexpr int SZ_B2 = 128;
constexpr int OFF_W3 = 93248;    constexpr int SZ_W3 = 256 * 128 * 9;  // 294912
constexpr int OFF_B3 = 388160;   constexpr int SZ_B3 = 256;
constexpr int OFF_W4 = 388416;   constexpr int SZ_W4 = 256 * 256 * 9;  // 589824
constexpr int OFF_B4 = 978240;   constexpr int SZ_B4 = 256;
constexpr int OFF_WO = 978496;   constexpr int SZ_WO = NCLS * FEAT;    // 409600
constexpr int OFF_BO = 1388096;  constexpr int SZ_BO = NCLS;
constexpr int PTOT   = 1388196;

// ---------------- static device scratch (no runtime alloc allowed) ----------------
__device__ float g_fw  [NB * PTOT];      // per-task fast weights
__device__ float g_grad[NB * PTOT];      // per-task grads (fully rewritten each step)
__device__ float g_a1[NB * 131072];
__device__ float g_a2[NB * 65536];
__device__ float g_a3[NB * 32768];
__device__ float g_a4[NB * 16384];
__device__ float g_a5[NB * 4096];
__device__ float g_feat[NB * FEAT];
__device__ float g_logit[NB * NCLS];
__device__ float g_dlogit[NB * NCLS];
__device__ float g_d1[NB * 131072];      // grad-activation ping
__device__ float g_d2[NB * 131072];      // grad-activation pong
__device__ float g_ta[NTEST * 131072];   // test act ping
__device__ float g_tb[NTEST * 131072];   // test act pong

// ---------------- kernels ----------------
__global__ void k_bcast(const float* __restrict__ src, float* __restrict__ fw, int off, int len)
{
    int i = blockIdx.x * 256 + threadIdx.x;
    if (i >= NB * len) return;
    int b = i / len, j = i % len;
    fw[(long)b * PTOT + off + j] = src[j];
}

// out = relu(conv3x3(in, w) + b); one thread per output element.
// wdiv: weight-set index = n / wdiv (1 for train, NL for test).
__global__ void k_conv_fwd(const float* __restrict__ in, long in_stride,
                           const float* __restrict__ fw, int woff, int boff, int wdiv,
                           float* __restrict__ out,
                           int N, int IC, int OC, int IH, int IW, int OH, int OW, int S)
{
    int idx = blockIdx.x * 256 + threadIdx.x;
    if (idx >= N * OC * OH * OW) return;
    int ox = idx % OW; int t = idx / OW;
    int oy = t % OH;   t /= OH;
    int oc = t % OC;   int n = t / OC;
    long ex = n / wdiv;
    const float* w = fw + ex * PTOT + woff + (long)oc * IC * 9;
    const float* x = in + (long)n * in_stride;
    float acc = fw[ex * PTOT + boff + oc];
    int iy0 = oy * S - 1, ix0 = ox * S - 1;
    for (int ic = 0; ic < IC; ic++) {
        const float* xc = x + (long)ic * IH * IW;
        const float* wc = w + ic * 9;
#pragma unroll
        for (int ky = 0; ky < 3; ky++) {
            int iy = iy0 + ky;
            if ((unsigned)iy >= (unsigned)IH) continue;
            const float* xr = xc + iy * IW;
#pragma unroll
            for (int kx = 0; kx < 3; kx++) {
                int ix = ix0 + kx;
                if ((unsigned)ix < (unsigned)IW)
                    acc = fmaf(xr[ix], wc[ky * 3 + kx], acc);
            }
        }
    }
    out[idx] = fmaxf(acc, 0.f);
}

__global__ void k_gate(const float* __restrict__ a, const float* __restrict__ gate, int gstride,
                       float* __restrict__ o, int N)
{
    int i = blockIdx.x * 256 + threadIdx.x;
    if (i >= N * FEAT) return;
    int n = i / FEAT, m = i % FEAT;
    o[i] = a[i] * gate[(long)n * gstride + m];
}

// logits[n, cls] = <W_out[cls,:], feat[n,:]> + b_out[cls]; one warp per (n, cls)
__global__ void k_head_fwd(const float* __restrict__ feat, const float* __restrict__ fw, int wdiv,
                           float* __restrict__ logits, int N)
{
    int gt = blockIdx.x * 256 + threadIdx.x;
    int warp = gt >> 5, lane = gt & 31;
    if (warp >= N * NCLS) return;
    int cls = warp % NCLS, n = warp / NCLS;
    long ex = n / wdiv;
    const float* w = fw + ex * PTOT + OFF_WO + (long)cls * FEAT;
    const float* f = feat + (long)n * FEAT;
    float acc = 0.f;
    for (int m = lane; m < FEAT; m += 32) acc = fmaf(w[m], f[m], acc);
#pragma unroll
    for (int o = 16; o; o >>= 1) acc += __shfl_down_sync(0xffffffffu, acc, o);
    if (!lane) logits[warp] = acc + fw[ex * PTOT + OFF_BO + cls];
}

// dlogit = softmax(logit) - onehot(y); one block (128 thr) per example
__global__ void k_ce_grad(const float* __restrict__ logits, const int* __restrict__ y,
                          int ystride, int yoff, float* __restrict__ dlogit)
{
    int b = blockIdx.x, tid = threadIdx.x;
    __shared__ float red[128];
    float v = (tid < NCLS) ? logits[b * NCLS + tid] : -1e30f;
    red[tid] = v; __syncthreads();
    for (int s = 64; s > 0; s >>= 1) { if (tid < s) red[tid] = fmaxf(red[tid], red[tid + s]); __syncthreads(); }
    float m = red[0]; __syncthreads();
    float e = (tid < NCLS) ? expf(v - m) : 0.f;
    red[tid] = e; __syncthreads();
    for (int s = 64; s > 0; s >>= 1) { if (tid < s) red[tid] += red[tid + s]; __syncthreads(); }
    float sum = red[0];
    int label = y[b * ystride + yoff];
    if (tid < NCLS) dlogit[b * NCLS + tid] = e / sum - (tid == label ? 1.f : 0.f);
}

__global__ void k_head_bwd_w(const float* __restrict__ dlogit, const float* __restrict__ feat,
                             float* __restrict__ grad)
{
    int i = blockIdx.x * 256 + threadIdx.x;
    if (i >= NB * NCLS * FEAT) return;
    int m = i % FEAT; int t = i / FEAT;
    int cls = t % NCLS; int b = t / NCLS;
    grad[(long)b * PTOT + OFF_WO + (long)cls * FEAT + m] =
        dlogit[b * NCLS + cls] * feat[(long)b * FEAT + m];
}

__global__ void k_head_bwd_b(const float* __restrict__ dlogit, float* __restrict__ grad)
{
    int i = blockIdx.x * 256 + threadIdx.x;
    if (i >= NB * NCLS) return;
    int b = i / NCLS, cls = i % NCLS;
    grad[(long)b * PTOT + OFF_BO + cls] = dlogit[i];
}

// dz5[b,m] = (a5>0) ? gate * sum_n Wout[n,m]*dlogit[n] : 0
__global__ void k_head_bwd_f(const float* __restrict__ dlogit, const float* __restrict__ fw,
                             const float* __restrict__ a5, const float* __restrict__ gate, int gstride,
                             float* __restrict__ dz)
{
    int i = blockIdx.x * 256 + threadIdx.x;
    if (i >= NB * FEAT) return;
    int m = i % FEAT, b = i / FEAT;
    float acc = 0.f;
    const float* w  = fw + (long)b * PTOT + OFF_WO + m;
    const float* dl = dlogit + b * NCLS;
    for (int n = 0; n < NCLS; n++) acc = fmaf(w[(long)n * FEAT], dl[n], acc);
    acc *= gate[(long)b * gstride + m];
    dz[i] = (a5[i] > 0.f) ? acc : 0.f;
}

// db[oc] = sum_{oy,ox} dz; one warp per (b, oc)
__global__ void k_conv_bwd_b(const float* __restrict__ dz, float* __restrict__ grad,
                             int boff, int OC, int OHW)
{
    int gt = blockIdx.x * 256 + threadIdx.x;
    int warp = gt >> 5, lane = gt & 31;
    if (warp >= NB * OC) return;
    int oc = warp % OC, b = warp / OC;
    const float* p = dz + ((long)b * OC + oc) * OHW;
    float acc = 0.f;
    for (int i = lane; i < OHW; i += 32) acc += p[i];
#pragma unroll
    for (int o = 16; o; o >>= 1) acc += __shfl_down_sync(0xffffffffu, acc, o);
    if (!lane) grad[(long)b * PTOT + boff + oc] = acc;
}

// dW[oc,ic,ky,kx] = sum_{oy,ox} dz[oc,oy,ox] * x[ic, oy*S+ky-1, ox*S+kx-1]
__global__ void k_conv_bwd_w(const float* __restrict__ dz, const float* __restrict__ xin, long in_stride,
                             float* __restrict__ grad, int woff,
                             int IC, int OC, int IH, int IW, int OH, int OW, int S)
{
    int idx = blockIdx.x * 256 + threadIdx.x;
    if (idx >= NB * OC * IC * 9) return;
    int k = idx % 9; int t = idx / 9;
    int ic = t % IC; t /= IC;
    int oc = t % OC; int b = t / OC;
    int ky = k / 3, kx = k % 3;
    const float* z = dz + ((long)b * OC + oc) * OH * OW;
    const float* x = xin + (long)b * in_stride + (long)ic * IH * IW;
    float acc = 0.f;
    for (int oy = 0; oy < OH; oy++) {
        int iy = oy * S + ky - 1;
        if ((unsigned)iy >= (unsigned)IH) continue;
        const float* xr = x + iy * IW;
        const float* zr = z + oy * OW;
        for (int ox = 0; ox < OW; ox++) {
            int ix = ox * S + kx - 1;
            if ((unsigned)ix < (unsigned)IW)
                acc = fmaf(zr[ox], xr[ix], acc);
        }
    }
    grad[(long)b * PTOT + woff + ((long)oc * IC + ic) * 9 + k] = acc;
}

// dx (masked by this layer's input activation a_in>0 -> becomes dZ of previous layer)
__global__ void k_conv_bwd_x(const float* __restrict__ dz, const float* __restrict__ fw, int woff,
                             const float* __restrict__ ain, float* __restrict__ dx,
                             int IC, int OC, int IH, int IW, int OH, int OW, int S)
{
    int idx = blockIdx.x * 256 + threadIdx.x;
    if (idx >= NB * IC * IH * IW) return;
    if (ain[idx] <= 0.f) { dx[idx] = 0.f; return; }
    int ix = idx % IW; int t = idx / IW;
    int iy = t % IH; t /= IH;
    int ic = t % IC; int b = t / IC;
    const float* w = fw + (long)b * PTOT + woff;
    const float* z = dz + (long)b * OC * OH * OW;
    float acc = 0.f;
#pragma unroll
    for (int ky = 0; ky < 3; ky++) {
        int ty = iy + 1 - ky;
        if (ty < 0 || (ty % S)) continue;
        int oy = ty / S;
        if (oy >= OH) continue;
#pragma unroll
        for (int kx = 0; kx < 3; kx++) {
            int tx = ix + 1 - kx;
            if (tx < 0 || (tx % S)) continue;
            int ox = tx / S;
            if (ox >= OW) continue;
            const float* wp = w + (long)ic * 9 + ky * 3 + kx;
            const float* zp = z + oy * OW + ox;
            for (int oc = 0; oc < OC; oc++)
                acc = fmaf(wp[(long)oc * IC * 9], zp[(long)oc * OH * OW], acc);
        }
    }
    dx[idx] = acc;
}

__global__ void k_sgd(float* __restrict__ fw, const float* __restrict__ grad,
                      const float* __restrict__ log_lr, int total)
{
    int i = blockIdx.x * 256 + threadIdx.x;
    if (i < total) fw[i] -= expf(*log_lr) * grad[i];
}

// per test example: loss = lse - logit[y]; eval = (argmax == y); also writes lr once
__global__ void k_loss_eval(const float* __restrict__ logits, const int* __restrict__ y,
                            const float* __restrict__ log_lr, float* __restrict__ out)
{
    int e = blockIdx.x, tid = threadIdx.x;
    __shared__ float rv[128];
    __shared__ int   ri[128];
    float v = (tid < NCLS) ? logits[e * NCLS + tid] : -1e30f;
    rv[tid] = v; ri[tid] = tid; __syncthreads();
    for (int s = 64; s > 0; s >>= 1) {
        if (tid < s) {
            if (rv[tid + s] > rv[tid] || (rv[tid + s] == rv[tid] && ri[tid + s] < ri[tid])) {
                rv[tid] = rv[tid + s]; ri[tid] = ri[tid + s];
            }
        }
        __syncthreads();
    }
    float m = rv[0]; int amax = ri[0]; __syncthreads();
    float ex = (tid < NCLS) ? expf(v - m) : 0.f;
    rv[tid] = ex; __syncthreads();
    for (int s = 64; s > 0; s >>= 1) { if (tid < s) rv[tid] += rv[tid + s]; __syncthreads(); }
    if (tid == 0) {
        float lse = m + logf(rv[0]);
        int label = y[e];
        out[e]        = lse - logits[e * NCLS + label];   // loss [B,L]
        out[129 + e]  = (amax == label) ? 1.f : 0.f;      // evaluation [B,L]
        if (e == 0) out[128] = expf(*log_lr);             // lr scalar
    }
}

// ---------------- launcher ----------------
struct LC { int ic, oc, ih, iw, oh, ow, s; };
static const LC lc[5] = {
    {  3,  32, 64, 64, 64, 64, 1},
    { 32,  64, 64, 64, 32, 32, 2},
    { 64, 128, 32, 32, 16, 16, 2},
    {128, 256, 16, 16,  8,  8, 2},
    {256, 256,  8,  8,  4,  4, 2},
};
static const int woffs[5] = {OFF_W0, OFF_W1, OFF_W2, OFF_W3, OFF_W4};
static const int boffs[5] = {OFF_B0, OFF_B1, OFF_B2, OFF_B3, OFF_B4};

static inline unsigned GRID(long n) { return (unsigned)((n + 255) / 256); }

extern "C" void kernel_launch(void* const* d_in, const int* in_sizes, int n_in,
                              void* d_out, int out_size)
{
    const float* pw[12];
    for (int i = 0; i < 12; i++) pw[i] = (const float*)d_in[i];
    const float* log_lr     = (const float*)d_in[12];
    const float* train_x    = (const float*)d_in[13];
    const float* test_x     = (const float*)d_in[14];
    const float* train_gate = (const float*)d_in[15];
    const float* test_gate  = (const float*)d_in[16];
    const int*   train_y    = (const int*)d_in[17];
    const int*   test_y     = (const int*)d_in[18];
    float* out = (float*)d_out;

    float *fw, *grad, *a1, *a2, *a3, *a4, *a5, *feat, *logit, *dlogit, *d1, *d2, *ta, *tb;
    cudaGetSymbolAddress((void**)&fw,     g_fw);
    cudaGetSymbolAddress((void**)&grad,   g_grad);
    cudaGetSymbolAddress((void**)&a1,     g_a1);
    cudaGetSymbolAddress((void**)&a2,     g_a2);
    cudaGetSymbolAddress((void**)&a3,     g_a3);
    cudaGetSymbolAddress((void**)&a4,     g_a4);
    cudaGetSymbolAddress((void**)&a5,     g_a5);
    cudaGetSymbolAddress((void**)&feat,   g_feat);
    cudaGetSymbolAddress((void**)&logit,  g_logit);
    cudaGetSymbolAddress((void**)&dlogit, g_dlogit);
    cudaGetSymbolAddress((void**)&d1,     g_d1);
    cudaGetSymbolAddress((void**)&d2,     g_d2);
    cudaGetSymbolAddress((void**)&ta,     g_ta);
    cudaGetSymbolAddress((void**)&tb,     g_tb);

    // 1) broadcast shared params into per-task fast weights
    const int offs[12] = {OFF_W0, OFF_B0, OFF_W1, OFF_B1, OFF_W2, OFF_B2,
                          OFF_W3, OFF_B3, OFF_W4, OFF_B4, OFF_WO, OFF_BO};
    const int szs[12]  = {SZ_W0, SZ_B0, SZ_W1, SZ_B1, SZ_W2, SZ_B2,
                          SZ_W3, SZ_B3, SZ_W4, SZ_B4, SZ_WO, SZ_BO};
    for (int i = 0; i < 12; i++)
        k_bcast<<<GRID((long)NB * szs[i]), 256>>>(pw[i], fw, offs[i], szs[i]);

    float* acts[6] = {nullptr, a1, a2, a3, a4, a5};

    // 2) inner loop: T SGD steps
    for (int t = 0; t < NT; t++) {
        const float* in0 = train_x + (long)t * CHW;
        // forward
        k_conv_fwd<<<GRID((long)NB * 32 * 64 * 64), 256>>>(
            in0, (long)NT * CHW, fw, OFF_W0, OFF_B0, 1, a1,
            NB, 3, 32, 64, 64, 64, 64, 1);
        for (int j = 1; j < 5; j++)
            k_conv_fwd<<<GRID((long)NB * lc[j].oc * lc[j].oh * lc[j].ow), 256>>>(
                acts[j], (long)lc[j].ic * lc[j].ih * lc[j].iw, fw, woffs[j], boffs[j], 1, acts[j + 1],
                NB, lc[j].ic, lc[j].oc, lc[j].ih, lc[j].iw, lc[j].oh, lc[j].ow, lc[j].s);
        k_gate<<<GRID((long)NB * FEAT), 256>>>(a5, train_gate + (long)t * FEAT, NT * FEAT, feat, NB);
        k_head_fwd<<<GRID((long)NB * NCLS * 32), 256>>>(feat, fw, 1, logit, NB);
        // backward
        k_ce_grad<<<NB, 128>>>(logit, train_y, NT, t, dlogit);
        k_head_bwd_w<<<GRID((long)NB * NCLS * FEAT), 256>>>(dlogit, feat, grad);
        k_head_bwd_b<<<GRID((long)NB * NCLS), 256>>>(dlogit, grad);
        k_head_bwd_f<<<GRID((long)NB * FEAT), 256>>>(dlogit, fw, a5,
                                                     train_gate + (long)t * FEAT, NT * FEAT, d1);
        float* dzb = d1; float* dxb = d2;
        for (int j = 4; j >= 1; j--) {
            k_conv_bwd_b<<<GRID((long)NB * lc[j].oc * 32), 256>>>(dzb, grad, boffs[j],
                                                                  lc[j].oc, lc[j].oh * lc[j].ow);
            k_conv_bwd_w<<<GRID((long)NB * lc[j].oc * lc[j].ic * 9), 256>>>(
                dzb, acts[j], (long)lc[j].ic * lc[j].ih * lc[j].iw, grad, woffs[j],
                lc[j].ic, lc[j].oc, lc[j].ih, lc[j].iw, lc[j].oh, lc[j].ow, lc[j].s);
            k_conv_bwd_x<<<GRID((long)NB * lc[j].ic * lc[j].ih * lc[j].iw), 256>>>(
                dzb, fw, woffs[j], acts[j], dxb,
                lc[j].ic, lc[j].oc, lc[j].ih, lc[j].iw, lc[j].oh, lc[j].ow, lc[j].s);
            float* tmp = dzb; dzb = dxb; dxb = tmp;
        }
        k_conv_bwd_b<<<GRID((long)NB * 32 * 32), 256>>>(dzb, grad, OFF_B0, 32, 64 * 64);
        k_conv_bwd_w<<<GRID((long)NB * 32 * 3 * 9), 256>>>(
            dzb, in0, (long)NT * CHW, grad, OFF_W0, 3, 32, 64, 64, 64, 64, 1);
        // SGD update of all fast weights
        k_sgd<<<GRID((long)NB * PTOT), 256>>>(fw, grad, log_lr, NB * PTOT);
    }

    // 3) test forward (128 examples, weight set = example/16), ping-pong buffers
    k_conv_fwd<<<GRID((long)NTEST * 32 * 64 * 64), 256>>>(
        test_x, (long)CHW, fw, OFF_W0, OFF_B0, NL, ta,
        NTEST, 3, 32, 64, 64, 64, 64, 1);
    k_conv_fwd<<<GRID((long)NTEST * 64 * 32 * 32), 256>>>(
        ta, (long)32 * 64 * 64, fw, OFF_W1, OFF_B1, NL, tb,
        NTEST, 32, 64, 64, 64, 32, 32, 2);
    k_conv_fwd<<<GRID((long)NTEST * 128 * 16 * 16), 256>>>(
        tb, (long)64 * 32 * 32, fw, OFF_W2, OFF_B2, NL, ta,
        NTEST, 64, 128, 32, 32, 16, 16, 2);
    k_conv_fwd<<<GRID((long)NTEST * 256 * 8 * 8), 256>>>(
        ta, (long)128 * 16 * 16, fw, OFF_W3, OFF_B3, NL, tb,
        NTEST, 128, 256, 16, 16, 8, 8, 2);
    k_conv_fwd<<<GRID((long)NTEST * 256 * 4 * 4), 256>>>(
        tb, (long)256 * 8 * 8, fw, OFF_W4, OFF_B4, NL, ta,
        NTEST, 256, 256, 8, 8, 4, 4, 2);
    k_gate<<<GRID((long)NTEST * FEAT), 256>>>(ta, test_gate, FEAT, tb, NTEST);
    k_head_fwd<<<GRID((long)NTEST * NCLS * 32), 256>>>(tb, fw, NL, out + 257, NTEST);
    k_loss_eval<<<NTEST, 128>>>(out + 257, test_y, log_lr, out);
}

// round 2
// speedup vs baseline: 1.3099x; 1.3099x over previous
#include <cuda_runtime.h>

// ---------------- problem constants ----------------
constexpr int NB    = 8;
constexpr int NT    = 5;
constexpr int NL    = 16;
constexpr int NTEST = NB * NL;          // 128
constexpr int NCLS  = 100;
constexpr int FEAT  = 4096;
constexpr int CHW   = 3 * 64 * 64;

constexpr int OFF_W0 = 0;        constexpr int SZ_W0 = 32 * 3 * 9;
constexpr int OFF_B0 = 864;      constexpr int SZ_B0 = 32;
constexpr int OFF_W1 = 896;      constexpr int SZ_W1 = 64 * 32 * 9;
constexpr int OFF_B1 = 19328;    constexpr int SZ_B1 = 64;
constexpr int OFF_W2 = 19392;    constexpr int SZ_W2 = 128 * 64 * 9;
constexpr int OFF_B2 = 93120;    constexpr int SZ_B2 = 128;
constexpr int OFF_W3 = 93248;    constexpr int SZ_W3 = 256 * 128 * 9;
constexpr int OFF_B3 = 388160;   constexpr int SZ_B3 = 256;
constexpr int OFF_W4 = 388416;   constexpr int SZ_W4 = 256 * 256 * 9;
constexpr int OFF_B4 = 978240;   constexpr int SZ_B4 = 256;
constexpr int OFF_WO = 978496;   constexpr int SZ_WO = NCLS * FEAT;
constexpr int OFF_BO = 1388096;  constexpr int SZ_BO = NCLS;
constexpr int PTOT   = 1388196;

// ---------------- static device scratch ----------------
__device__ float g_fw  [NB * PTOT];
__device__ float g_grad[NB * PTOT];
__device__ float g_a1[NB * 131072];
__device__ float g_a2[NB * 65536];
__device__ float g_a3[NB * 32768];
__device__ float g_a4[NB * 16384];
__device__ float g_a5[NB * 4096];
__device__ float g_feat[NB * FEAT];
__device__ float g_logit[NB * NCLS];
__device__ float g_dlogit[NB * NCLS];
__device__ float g_d1[NB * 131072];
__device__ float g_d2[NB * 131072];
__device__ float g_ta[NTEST * 131072];
__device__ float g_tb[NTEST * 131072];

// ---------------- kernels ----------------
__global__ void k_bcast(const float* __restrict__ src, float* __restrict__ fw, int off, int len)
{
    int i = blockIdx.x * 256 + threadIdx.x;
    if (i >= NB * len) return;
    int b = i / len, j = i % len;
    fw[(long)b * PTOT + off + j] = src[j];
}

__global__ void k_zero(float* __restrict__ grad, int off, int len)
{
    int i = blockIdx.x * 256 + threadIdx.x;
    if (i >= NB * len) return;
    grad[(long)(i / len) * PTOT + off + (i % len)] = 0.f;
}

// Register-tiled conv fwd: each thread computes TOC x TOX outputs.
template<int S, int TOC, int TOX>
__global__ void k_conv_fwd_t(const float* __restrict__ in, long in_stride,
                             const float* __restrict__ fw, int woff, int boff, int wdiv,
                             float* __restrict__ out,
                             int N, int IC, int OC, int IH, int IW, int OH, int OW)
{
    constexpr int XLEN = (TOX - 1) * S + 3;
    int idx = blockIdx.x * 256 + threadIdx.x;
    int nox = OW / TOX;
    int noc = OC / TOC;
    if (idx >= N * noc * OH * nox) return;
    int ox0 = (idx % nox) * TOX; int t = idx / nox;
    int oy  = t % OH;            t /= OH;
    int oc0 = (t % noc) * TOC;   int n = t / noc;
    long ex = n / wdiv;
    const float* wbase = fw + ex * PTOT + woff;
    const float* x     = in + (long)n * in_stride;

    float acc[TOC][TOX];
#pragma unroll
    for (int i = 0; i < TOC; i++) {
        float bv = fw[ex * PTOT + boff + oc0 + i];
#pragma unroll
        for (int j = 0; j < TOX; j++) acc[i][j] = bv;
    }
    int ixb = ox0 * S - 1;
    for (int ic = 0; ic < IC; ic++) {
        const float* xc = x + (long)ic * IH * IW;
#pragma unroll
        for (int ky = 0; ky < 3; ky++) {
            int iy = oy * S - 1 + ky;
            if ((unsigned)iy >= (unsigned)IH) continue;
            const float* xr = xc + iy * IW;
            float xv[XLEN];
#pragma unroll
            for (int u = 0; u < XLEN; u++) {
                int ix = ixb + u;
                xv[u] = ((unsigned)ix < (unsigned)IW) ? xr[ix] : 0.f;
            }
#pragma unroll
            for (int i = 0; i < TOC; i++) {
                const float* wp = wbase + ((long)(oc0 + i) * IC + ic) * 9 + ky * 3;
                float w0 = wp[0], w1 = wp[1], w2 = wp[2];
#pragma unroll
                for (int j = 0; j < TOX; j++)
                    acc[i][j] = fmaf(w0, xv[j * S],
                                fmaf(w1, xv[j * S + 1],
                                fmaf(w2, xv[j * S + 2], acc[i][j])));
            }
        }
    }
#pragma unroll
    for (int i = 0; i < TOC; i++) {
        float* op = out + (((long)n * OC + oc0 + i) * OH + oy) * OW + ox0;
#pragma unroll
        for (int j = 0; j < TOX; j++) op[j] = fmaxf(acc[i][j], 0.f);
    }
}

__global__ void k_gate(const float* __restrict__ a, const float* __restrict__ gate, int gstride,
                       float* __restrict__ o, int N)
{
    int i = blockIdx.x * 256 + threadIdx.x;
    if (i >= N * FEAT) return;
    int n = i / FEAT, m = i % FEAT;
    o[i] = a[i] * gate[(long)n * gstride + m];
}

__global__ void k_head_fwd(const float* __restrict__ feat, const float* __restrict__ fw, int wdiv,
                           float* __restrict__ logits, int N)
{
    int gt = blockIdx.x * 256 + threadIdx.x;
    int warp = gt >> 5, lane = gt & 31;
    if (warp >= N * NCLS) return;
    int cls = warp % NCLS, n = warp / NCLS;
    long ex = n / wdiv;
    const float* w = fw + ex * PTOT + OFF_WO + (long)cls * FEAT;
    const float* f = feat + (long)n * FEAT;
    float acc = 0.f;
    for (int m = lane; m < FEAT; m += 32) acc = fmaf(w[m], f[m], acc);
#pragma unroll
    for (int o = 16; o; o >>= 1) acc += __shfl_down_sync(0xffffffffu, acc, o);
    if (!lane) logits[warp] = acc + fw[ex * PTOT + OFF_BO + cls];
}

__global__ void k_ce_grad(const float* __restrict__ logits, const int* __restrict__ y,
                          int ystride, int yoff, float* __restrict__ dlogit)
{
    int b = blockIdx.x, tid = threadIdx.x;
    __shared__ float red[128];
    float v = (tid < NCLS) ? logits[b * NCLS + tid] : -1e30f;
    red[tid] = v; __syncthreads();
    for (int s = 64; s > 0; s >>= 1) { if (tid < s) red[tid] = fmaxf(red[tid], red[tid + s]); __syncthreads(); }
    float m = red[0]; __syncthreads();
    float e = (tid < NCLS) ? expf(v - m) : 0.f;
    red[tid] = e; __syncthreads();
    for (int s = 64; s > 0; s >>= 1) { if (tid < s) red[tid] += red[tid + s]; __syncthreads(); }
    float sum = red[0];
    int label = y[b * ystride + yoff];
    if (tid < NCLS) dlogit[b * NCLS + tid] = e / sum - (tid == label ? 1.f : 0.f);
}

__global__ void k_head_bwd_w(const float* __restrict__ dlogit, const float* __restrict__ feat,
                             float* __restrict__ grad)
{
    int i = blockIdx.x * 256 + threadIdx.x;
    if (i >= NB * NCLS * FEAT) return;
    int m = i % FEAT; int t = i / FEAT;
    int cls = t % NCLS; int b = t / NCLS;
    grad[(long)b * PTOT + OFF_WO + (long)cls * FEAT + m] =
        dlogit[b * NCLS + cls] * feat[(long)b * FEAT + m];
}

__global__ void k_head_bwd_b(const float* __restrict__ dlogit, float* __restrict__ grad)
{
    int i = blockIdx.x * 256 + threadIdx.x;
    if (i >= NB * NCLS) return;
    int b = i / NCLS, cls = i % NCLS;
    grad[(long)b * PTOT + OFF_BO + cls] = dlogit[i];
}

__global__ void k_head_bwd_f(const float* __restrict__ dlogit, const float* __restrict__ fw,
                             const float* __restrict__ a5, const float* __restrict__ gate, int gstride,
                             float* __restrict__ dz)
{
    int i = blockIdx.x * 256 + threadIdx.x;
    if (i >= NB * FEAT) return;
    int m = i % FEAT, b = i / FEAT;
    float acc = 0.f;
    const float* w  = fw + (long)b * PTOT + OFF_WO + m;
    const float* dl = dlogit + b * NCLS;
    for (int n = 0; n < NCLS; n++) acc = fmaf(w[(long)n * FEAT], dl[n], acc);
    acc *= gate[(long)b * gstride + m];
    dz[i] = (a5[i] > 0.f) ? acc : 0.f;
}

__global__ void k_conv_bwd_b(const float* __restrict__ dz, float* __restrict__ grad,
                             int boff, int OC, int OHW)
{
    int gt = blockIdx.x * 256 + threadIdx.x;
    int warp = gt >> 5, lane = gt & 31;
    if (warp >= NB * OC) return;
    int oc = warp % OC, b = warp / OC;
    const float* p = dz + ((long)b * OC + oc) * OHW;
    float acc = 0.f;
    for (int i = lane; i < OHW; i += 32) acc += p[i];
#pragma unroll
    for (int o = 16; o; o >>= 1) acc += __shfl_down_sync(0xffffffffu, acc, o);
    if (!lane) grad[(long)b * PTOT + boff + oc] = acc;
}

// bwd_w: thread owns (b, oc, ic, ky, oy-chunk); sliding 3-wide x window per row.
template<int S, bool ATOMIC>
__global__ void k_conv_bwd_w_t(const float* __restrict__ dz, const float* __restrict__ xin, long in_stride,
                               float* __restrict__ grad, int woff,
                               int IC, int OC, int IH, int IW, int OH, int OW, int NCH, int CH)
{
    int idx = blockIdx.x * 256 + threadIdx.x;
    if (idx >= NB * OC * IC * 3 * NCH) return;
    int c  = idx % NCH; int t = idx / NCH;
    int ky = t % 3;  t /= 3;
    int ic = t % IC; t /= IC;
    int oc = t % OC; int b = t / OC;
    const float* x = xin + (long)b * in_stride + (long)ic * IH * IW;
    const float* z = dz + ((long)b * OC + oc) * OH * OW;
    float a0 = 0.f, a1 = 0.f, a2 = 0.f;
    int oy0 = c * CH;
    for (int oy = oy0; oy < oy0 + CH; oy++) {
        int iy = oy * S + ky - 1;
        if ((unsigned)iy >= (unsigned)IH) continue;
        const float* xr = x + iy * IW;
        const float* zr = z + oy * OW;
        if (S == 1) {
            float w0 = 0.f, w1 = xr[0], w2;
            for (int ox = 0; ox < OW; ox++) {
                w2 = (ox + 1 < IW) ? xr[ox + 1] : 0.f;
                float zv = zr[ox];
                a0 = fmaf(zv, w0, a0); a1 = fmaf(zv, w1, a1); a2 = fmaf(zv, w2, a2);
                w0 = w1; w1 = w2;
            }
        } else {
            float carry = 0.f;   // x[2*ox-1], starts as x[-1]=0
            for (int ox = 0; ox < OW; ox++) {
                float w0 = carry;
                float w1 = xr[2 * ox];
                float w2 = xr[2 * ox + 1];
                float zv = zr[ox];
                a0 = fmaf(zv, w0, a0); a1 = fmaf(zv, w1, a1); a2 = fmaf(zv, w2, a2);
                carry = w2;
            }
        }
    }
    float* g = grad + (long)b * PTOT + woff + ((long)oc * IC + ic) * 9 + ky * 3;
    if (ATOMIC) { atomicAdd(g, a0); atomicAdd(g + 1, a1); atomicAdd(g + 2, a2); }
    else        { g[0] = a0; g[1] = a1; g[2] = a2; }
}

// bwd_x (stride-2 layers only): 4 consecutive input pixels per thread.
__global__ void k_conv_bwd_x4(const float* __restrict__ dz, const float* __restrict__ fw, int woff,
                              const float* __restrict__ ain, float* __restrict__ dx,
                              int IC, int OC, int IH, int IW, int OH, int OW)
{
    int idx = blockIdx.x * 256 + threadIdx.x;
    int nix = IW >> 2;
    if (idx >= NB * IC * IH * nix) return;
    int ix0 = (idx % nix) * 4; int t = idx / nix;
    int iy = t % IH; t /= IH;
    int ic = t % IC; int b = t / IC;
    long pix = (((long)b * IC + ic) * IH + iy) * IW + ix0;

    float m0 = ain[pix], m1 = ain[pix + 1], m2 = ain[pix + 2], m3 = ain[pix + 3];
    float acc0 = 0.f, acc1 = 0.f, acc2 = 0.f, acc3 = 0.f;
    int ox0p = ix0 >> 1;
    bool ok2 = (ox0p + 2 < OW), ok1 = (ox0p + 1 < OW);

    int oyv[3]; bool kyok[3];
#pragma unroll
    for (int ky = 0; ky < 3; ky++) {
        int ty = iy + 1 - ky;
        kyok[ky] = (ty >= 0) && !(ty & 1) && ((ty >> 1) < OH);
        oyv[ky] = ty >> 1;
    }
    const float* wb = fw + (long)b * PTOT + woff + (long)ic * 9;
    const float* zb = dz + (long)b * OC * OH * OW;
    for (int oc = 0; oc < OC; oc++) {
        const float* wp = wb + (long)oc * IC * 9;
        const float* zp = zb + (long)oc * OH * OW;
#pragma unroll
        for (int ky = 0; ky < 3; ky++) {
            if (!kyok[ky]) continue;
            const float* zr = zp + oyv[ky] * OW;
            float d0 = zr[ox0p];
            float d1 = ok1 ? zr[ox0p + 1] : 0.f;
            float d2 = ok2 ? zr[ox0p + 2] : 0.f;
            float wk0 = wp[ky * 3 + 0], wk1 = wp[ky * 3 + 1], wk2 = wp[ky * 3 + 2];
            acc0 = fmaf(wk1, d0, acc0);
            acc1 = fmaf(wk0, d1, fmaf(wk2, d0, acc1));
            acc2 = fmaf(wk1, d1, acc2);
            acc3 = fmaf(wk0, d2, fmaf(wk2, d1, acc3));
        }
    }
    dx[pix]     = (m0 > 0.f) ? acc0 : 0.f;
    dx[pix + 1] = (m1 > 0.f) ? acc1 : 0.f;
    dx[pix + 2] = (m2 > 0.f) ? acc2 : 0.f;
    dx[pix + 3] = (m3 > 0.f) ? acc3 : 0.f;
}

__global__ void k_sgd(float* __restrict__ fw, const float* __restrict__ grad,
                      const float* __restrict__ log_lr, int total)
{
    int i = blockIdx.x * 256 + threadIdx.x;
    if (i < total) fw[i] -= expf(*log_lr) * grad[i];
}

__global__ void k_loss_eval(const float* __restrict__ logits, const int* __restrict__ y,
                            const float* __restrict__ log_lr, float* __restrict__ out)
{
    int e = blockIdx.x, tid = threadIdx.x;
    __shared__ float rv[128];
    __shared__ int   ri[128];
    float v = (tid < NCLS) ? logits[e * NCLS + tid] : -1e30f;
    rv[tid] = v; ri[tid] = tid; __syncthreads();
    for (int s = 64; s > 0; s >>= 1) {
        if (tid < s) {
            if (rv[tid + s] > rv[tid] || (rv[tid + s] == rv[tid] && ri[tid + s] < ri[tid])) {
                rv[tid] = rv[tid + s]; ri[tid] = ri[tid + s];
            }
        }
        __syncthreads();
    }
    float m = rv[0]; int amax = ri[0]; __syncthreads();
    float ex = (tid < NCLS) ? expf(v - m) : 0.f;
    rv[tid] = ex; __syncthreads();
    for (int s = 64; s > 0; s >>= 1) { if (tid < s) rv[tid] += rv[tid + s]; __syncthreads(); }
    if (tid == 0) {
        float lse = m + logf(rv[0]);
        int label = y[e];
        out[e]        = lse - logits[e * NCLS + label];
        out[129 + e]  = (amax == label) ? 1.f : 0.f;
        if (e == 0) out[128] = expf(*log_lr);
    }
}

// ---------------- launcher ----------------
struct LC { int ic, oc, ih, iw, oh, ow, s; };
static const LC lc[5] = {
    {  3,  32, 64, 64, 64, 64, 1},
    { 32,  64, 64, 64, 32, 32, 2},
    { 64, 128, 32, 32, 16, 16, 2},
    {128, 256, 16, 16,  8,  8, 2},
    {256, 256,  8,  8,  4,  4, 2},
};
static const int woffs[5] = {OFF_W0, OFF_W1, OFF_W2, OFF_W3, OFF_W4};
static const int boffs[5] = {OFF_B0, OFF_B1, OFF_B2, OFF_B3, OFF_B4};

static inline unsigned GRID(long n) { return (unsigned)((n + 255) / 256); }

// helper: launch tiled fwd conv for layer j
#define FWD(Tmpl, IN, INSTRIDE, J, WDIV, OUT, N)                                        \
    do {                                                                                \
        long tot_ = (long)(N) * (lc[J].oc / Tmpl##_TOC) * lc[J].oh * (lc[J].ow / Tmpl##_TOX); \
        k_conv_fwd_t<Tmpl##_S, Tmpl##_TOC, Tmpl##_TOX><<<GRID(tot_), 256>>>(            \
            IN, INSTRIDE, fw, woffs[J], boffs[J], WDIV, OUT,                            \
            N, lc[J].ic, lc[J].oc, lc[J].ih, lc[J].iw, lc[J].oh, lc[J].ow);             \
    } while (0)

#define T144_S 1
#define T144_TOC 4
#define T144_TOX 4
#define T244_S 2
#define T244_TOC 4
#define T244_TOX 4
#define T224_S 2
#define T224_TOC 2
#define T224_TOX 4
#define T222_S 2
#define T222_TOC 2
#define T222_TOX 2
#define T221_S 2
#define T221_TOC 2
#define T221_TOX 1

extern "C" void kernel_launch(void* const* d_in, const int* in_sizes, int n_in,
                              void* d_out, int out_size)
{
    const float* pw[12];
    for (int i = 0; i < 12; i++) pw[i] = (const float*)d_in[i];
    const float* log_lr     = (const float*)d_in[12];
    const float* train_x    = (const float*)d_in[13];
    const float* test_x     = (const float*)d_in[14];
    const float* train_gate = (const float*)d_in[15];
    const float* test_gate  = (const float*)d_in[16];
    const int*   train_y    = (const int*)d_in[17];
    const int*   test_y     = (const int*)d_in[18];
    float* out = (float*)d_out;

    float *fw, *grad, *a1, *a2, *a3, *a4, *a5, *feat, *logit, *dlogit, *d1, *d2, *ta, *tb;
    cudaGetSymbolAddress((void**)&fw,     g_fw);
    cudaGetSymbolAddress((void**)&grad,   g_grad);
    cudaGetSymbolAddress((void**)&a1,     g_a1);
    cudaGetSymbolAddress((void**)&a2,     g_a2);
    cudaGetSymbolAddress((void**)&a3,     g_a3);
    cudaGetSymbolAddress((void**)&a4,     g_a4);
    cudaGetSymbolAddress((void**)&a5,     g_a5);
    cudaGetSymbolAddress((void**)&feat,   g_feat);
    cudaGetSymbolAddress((void**)&logit,  g_logit);
    cudaGetSymbolAddress((void**)&dlogit, g_dlogit);
    cudaGetSymbolAddress((void**)&d1,     g_d1);
    cudaGetSymbolAddress((void**)&d2,     g_d2);
    cudaGetSymbolAddress((void**)&ta,     g_ta);
    cudaGetSymbolAddress((void**)&tb,     g_tb);

    const int offs[12] = {OFF_W0, OFF_B0, OFF_W1, OFF_B1, OFF_W2, OFF_B2,
                          OFF_W3, OFF_B3, OFF_W4, OFF_B4, OFF_WO, OFF_BO};
    const int szs[12]  = {SZ_W0, SZ_B0, SZ_W1, SZ_B1, SZ_W2, SZ_B2,
                          SZ_W3, SZ_B3, SZ_W4, SZ_B4, SZ_WO, SZ_BO};
    for (int i = 0; i < 12; i++)
        k_bcast<<<GRID((long)NB * szs[i]), 256>>>(pw[i], fw, offs[i], szs[i]);

    float* acts[6] = {nullptr, a1, a2, a3, a4, a5};

    // -------- inner loop --------
    for (int t = 0; t < NT; t++) {
        const float* in0 = train_x + (long)t * CHW;
        // forward
        FWD(T144, in0, (long)NT * CHW, 0, 1, a1, NB);
        FWD(T244, a1, (long)32 * 64 * 64, 1, 1, a2, NB);
        FWD(T224, a2, (long)64 * 32 * 32, 2, 1, a3, NB);
        FWD(T222, a3, (long)128 * 16 * 16, 3, 1, a4, NB);
        FWD(T221, a4, (long)256 * 8 * 8, 4, 1, a5, NB);
        k_gate<<<GRID((long)NB * FEAT), 256>>>(a5, train_gate + (long)t * FEAT, NT * FEAT, feat, NB);
        k_head_fwd<<<GRID((long)NB * NCLS * 32), 256>>>(feat, fw, 1, logit, NB);
        // backward
        k_ce_grad<<<NB, 128>>>(logit, train_y, NT, t, dlogit);
        k_zero<<<GRID((long)NB * SZ_W0), 256>>>(grad, OFF_W0, SZ_W0);
        k_zero<<<GRID((long)NB * SZ_W1), 256>>>(grad, OFF_W1, SZ_W1);
        k_head_bwd_w<<<GRID((long)NB * NCLS * FEAT), 256>>>(dlogit, feat, grad);
        k_head_bwd_b<<<GRID((long)NB * NCLS), 256>>>(dlogit, grad);
        k_head_bwd_f<<<GRID((long)NB * FEAT), 256>>>(dlogit, fw, a5,
                                                     train_gate + (long)t * FEAT, NT * FEAT, d1);
        float* dzb = d1; float* dxb = d2;
        for (int j = 4; j >= 1; j--) {
            k_conv_bwd_b<<<GRID((long)NB * lc[j].oc * 32), 256>>>(dzb, grad, boffs[j],
                                                                  lc[j].oc, lc[j].oh * lc[j].ow);
            if (j == 1) {
                int NCH = 4, CH = lc[j].oh / 4;
                k_conv_bwd_w_t<2, true><<<GRID((long)NB * lc[j].oc * lc[j].ic * 3 * NCH), 256>>>(
                    dzb, acts[j], (long)lc[j].ic * lc[j].ih * lc[j].iw, grad, woffs[j],
                    lc[j].ic, lc[j].oc, lc[j].ih, lc[j].iw, lc[j].oh, lc[j].ow, NCH, CH);
            } else {
                k_conv_bwd_w_t<2, false><<<GRID((long)NB * lc[j].oc * lc[j].ic * 3), 256>>>(
                    dzb, acts[j], (long)lc[j].ic * lc[j].ih * lc[j].iw, grad, woffs[j],
                    lc[j].ic, lc[j].oc, lc[j].ih, lc[j].iw, lc[j].oh, lc[j].ow, 1, lc[j].oh);
            }
            k_conv_bwd_x4<<<GRID((long)NB * lc[j].ic * lc[j].ih * (lc[j].iw / 4)), 256>>>(
                dzb, fw, woffs[j], acts[j], dxb,
                lc[j].ic, lc[j].oc, lc[j].ih, lc[j].iw, lc[j].oh, lc[j].ow);
            float* tmp = dzb; dzb = dxb; dxb = tmp;
        }
        k_conv_bwd_b<<<GRID((long)NB * 32 * 32), 256>>>(dzb, grad, OFF_B0, 32, 64 * 64);
        {
            int NCH = 16, CH = 64 / 16;
            k_conv_bwd_w_t<1, true><<<GRID((long)NB * 32 * 3 * 3 * NCH), 256>>>(
                dzb, in0, (long)NT * CHW, grad, OFF_W0,
                3, 32, 64, 64, 64, 64, NCH, CH);
        }
        k_sgd<<<GRID((long)NB * PTOT), 256>>>(fw, grad, log_lr, NB * PTOT);
    }

    // -------- test forward --------
    FWD(T144, test_x, (long)CHW, 0, NL, ta, NTEST);
    FWD(T244, ta, (long)32 * 64 * 64, 1, NL, tb, NTEST);
    FWD(T244, tb, (long)64 * 32 * 32, 2, NL, ta, NTEST);
    FWD(T244, ta, (long)128 * 16 * 16, 3, NL, tb, NTEST);
    FWD(T244, tb, (long)256 * 8 * 8, 4, NL, ta, NTEST);
    k_gate<<<GRID((long)NTEST * FEAT), 256>>>(ta, test_gate, FEAT, tb, NTEST);
    k_head_fwd<<<GRID((long)NTEST * NCLS * 32), 256>>>(tb, fw, NL, out + 257, NTEST);
    k_loss_eval<<<NTEST, 128>>>(out + 257, test_y, log_lr, out);
}

// round 3
// speedup vs baseline: 1.4515x; 1.1081x over previous
#include <cuda_runtime.h>

// ---------------- problem constants ----------------
constexpr int NB    = 8;
constexpr int NT    = 5;
constexpr int NL    = 16;
constexpr int NTEST = NB * NL;          // 128
constexpr int NCLS  = 100;
constexpr int FEAT  = 4096;
constexpr int CHW   = 3 * 64 * 64;

constexpr int OFF_W0 = 0;        constexpr int SZ_W0 = 32 * 3 * 9;
constexpr int OFF_B0 = 864;      constexpr int SZ_B0 = 32;
constexpr int OFF_W1 = 896;      constexpr int SZ_W1 = 64 * 32 * 9;
constexpr int OFF_B1 = 19328;    constexpr int SZ_B1 = 64;
constexpr int OFF_W2 = 19392;    constexpr int SZ_W2 = 128 * 64 * 9;
constexpr int OFF_B2 = 93120;    constexpr int SZ_B2 = 128;
constexpr int OFF_W3 = 93248;    constexpr int SZ_W3 = 256 * 128 * 9;
constexpr int OFF_B3 = 388160;   constexpr int SZ_B3 = 256;
constexpr int OFF_W4 = 388416;   constexpr int SZ_W4 = 256 * 256 * 9;
constexpr int OFF_B4 = 978240;   constexpr int SZ_B4 = 256;
constexpr int OFF_WO = 978496;   constexpr int SZ_WO = NCLS * FEAT;
constexpr int OFF_BO = 1388096;  constexpr int SZ_BO = NCLS;
constexpr int PTOT   = 1388196;

// ---------------- static device scratch ----------------
__device__ float g_fw  [NB * PTOT];
__device__ float g_a1[NB * 131072];
__device__ float g_a2[NB * 65536];
__device__ float g_a3[NB * 32768];
__device__ float g_a4[NB * 16384];
__device__ float g_a5[NB * 4096];
__device__ float g_feat[NB * FEAT];
__device__ float g_logit[NB * NCLS];
__device__ float g_dlogit[NB * NCLS];
__device__ float g_d1[NB * 131072];   // dz (current layer grad-activation)
__device__ float g_d2[NB * 131072];   // raw dx accumulation
__device__ float g_ta[NTEST * 131072];
__device__ float g_tb[NTEST * 131072];

// ---------------- generic kernels ----------------
__global__ void k_bcast(const float* __restrict__ src, float* __restrict__ fw, int off, int len)
{
    int i = blockIdx.x * 256 + threadIdx.x;
    if (i >= NB * len) return;
    int b = i / len, j = i % len;
    fw[(long)b * PTOT + off + j] = src[j];
}

// Direct tiled conv fwd with fused bias+relu (for layers with small IC).
template<int S, int TOC, int TOX>
__global__ void k_conv_fwd_t(const float* __restrict__ in, long in_stride,
                             const float* __restrict__ fw, int woff, int boff, int wdiv,
                             float* __restrict__ out,
                             int N, int IC, int OC, int IH, int IW, int OH, int OW)
{
    constexpr int XLEN = (TOX - 1) * S + 3;
    int idx = blockIdx.x * 256 + threadIdx.x;
    int nox = OW / TOX;
    int noc = OC / TOC;
    if (idx >= N * noc * OH * nox) return;
    int ox0 = (idx % nox) * TOX; int t = idx / nox;
    int oy  = t % OH;            t /= OH;
    int oc0 = (t % noc) * TOC;   int n = t / noc;
    long ex = n / wdiv;
    const float* wbase = fw + ex * PTOT + woff;
    const float* x     = in + (long)n * in_stride;

    float acc[TOC][TOX];
#pragma unroll
    for (int i = 0; i < TOC; i++) {
        float bv = fw[ex * PTOT + boff + oc0 + i];
#pragma unroll
        for (int j = 0; j < TOX; j++) acc[i][j] = bv;
    }
    int ixb = ox0 * S - 1;
    for (int ic = 0; ic < IC; ic++) {
        const float* xc = x + (long)ic * IH * IW;
#pragma unroll
        for (int ky = 0; ky < 3; ky++) {
            int iy = oy * S - 1 + ky;
            if ((unsigned)iy >= (unsigned)IH) continue;
            const float* xr = xc + iy * IW;
            float xv[XLEN];
#pragma unroll
            for (int u = 0; u < XLEN; u++) {
                int ix = ixb + u;
                xv[u] = ((unsigned)ix < (unsigned)IW) ? xr[ix] : 0.f;
            }
#pragma unroll
            for (int i = 0; i < TOC; i++) {
                const float* wp = wbase + ((long)(oc0 + i) * IC + ic) * 9 + ky * 3;
                float w0 = wp[0], w1 = wp[1], w2 = wp[2];
#pragma unroll
                for (int j = 0; j < TOX; j++)
                    acc[i][j] = fmaf(w0, xv[j * S],
                                fmaf(w1, xv[j * S + 1],
                                fmaf(w2, xv[j * S + 2], acc[i][j])));
            }
        }
    }
#pragma unroll
    for (int i = 0; i < TOC; i++) {
        float* op = out + (((long)n * OC + oc0 + i) * OH + oy) * OW + ox0;
#pragma unroll
        for (int j = 0; j < TOX; j++) op[j] = fmaxf(acc[i][j], 0.f);
    }
}

// IC-chunked conv fwd: atomic partial sums into zeroed out buffer (no bias/relu).
template<int S, int TOC, int TOX>
__global__ void k_conv_fwd_chunk(const float* __restrict__ in, long in_stride,
                                 const float* __restrict__ fw, int woff, int wdiv,
                                 float* __restrict__ out,
                                 int N, int IC, int OC, int IH, int IW, int OH, int OW,
                                 int NCHUNK, int ICH)
{
    constexpr int XLEN = (TOX - 1) * S + 3;
    int nox = OW / TOX;
    int noc = OC / TOC;
    int base = N * noc * OH * nox;
    int idx = blockIdx.x * 256 + threadIdx.x;
    if (idx >= base * NCHUNK) return;
    int ch = idx / base; int r = idx % base;
    int ox0 = (r % nox) * TOX; int t = r / nox;
    int oy  = t % OH;          t /= OH;
    int oc0 = (t % noc) * TOC; int n = t / noc;
    long ex = n / wdiv;
    const float* wbase = fw + ex * PTOT + woff;
    const float* x     = in + (long)n * in_stride;

    float acc[TOC][TOX];
#pragma unroll
    for (int i = 0; i < TOC; i++)
#pragma unroll
        for (int j = 0; j < TOX; j++) acc[i][j] = 0.f;

    int ixb = ox0 * S - 1;
    int ic0 = ch * ICH;
    for (int ic = ic0; ic < ic0 + ICH; ic++) {
        const float* xc = x + (long)ic * IH * IW;
#pragma unroll
        for (int ky = 0; ky < 3; ky++) {
            int iy = oy * S - 1 + ky;
            if ((unsigned)iy >= (unsigned)IH) continue;
            const float* xr = xc + iy * IW;
            float xv[XLEN];
#pragma unroll
            for (int u = 0; u < XLEN; u++) {
                int ix = ixb + u;
                xv[u] = ((unsigned)ix < (unsigned)IW) ? xr[ix] : 0.f;
            }
#pragma unroll
            for (int i = 0; i < TOC; i++) {
                const float* wp = wbase + ((long)(oc0 + i) * IC + ic) * 9 + ky * 3;
                float w0 = wp[0], w1 = wp[1], w2 = wp[2];
#pragma unroll
                for (int j = 0; j < TOX; j++)
                    acc[i][j] = fmaf(w0, xv[j * S],
                                fmaf(w1, xv[j * S + 1],
                                fmaf(w2, xv[j * S + 2], acc[i][j])));
            }
        }
    }
#pragma unroll
    for (int i = 0; i < TOC; i++) {
        float* op = out + (((long)n * OC + oc0 + i) * OH + oy) * OW + ox0;
#pragma unroll
        for (int j = 0; j < TOX; j++) atomicAdd(op + j, acc[i][j]);
    }
}

// in-place: out = relu(out + bias[oc])
__global__ void k_biasrelu(float* __restrict__ out, const float* __restrict__ fw,
                           int boff, int wdiv, int N, int OC, int OHW)
{
    int i = blockIdx.x * 256 + threadIdx.x;
    if (i >= N * OC * OHW) return;
    int oc = (i / OHW) % OC;
    long ex = (i / (OC * OHW)) / wdiv;
    out[i] = fmaxf(out[i] + fw[ex * PTOT + boff + oc], 0.f);
}

__global__ void k_gate(const float* __restrict__ a, const float* __restrict__ gate, int gstride,
                       float* __restrict__ o, int N)
{
    int i = blockIdx.x * 256 + threadIdx.x;
    if (i >= N * FEAT) return;
    int n = i / FEAT, m = i % FEAT;
    o[i] = a[i] * gate[(long)n * gstride + m];
}

__global__ void k_head_fwd(const float* __restrict__ feat, const float* __restrict__ fw, int wdiv,
                           float* __restrict__ logits, int N)
{
    int gt = blockIdx.x * 256 + threadIdx.x;
    int warp = gt >> 5, lane = gt & 31;
    if (warp >= N * NCLS) return;
    int cls = warp % NCLS, n = warp / NCLS;
    long ex = n / wdiv;
    const float* w = fw + ex * PTOT + OFF_WO + (long)cls * FEAT;
    const float* f = feat + (long)n * FEAT;
    float acc = 0.f;
    for (int m = lane; m < FEAT; m += 32) acc = fmaf(w[m], f[m], acc);
#pragma unroll
    for (int o = 16; o; o >>= 1) acc += __shfl_down_sync(0xffffffffu, acc, o);
    if (!lane) logits[warp] = acc + fw[ex * PTOT + OFF_BO + cls];
}

// dlogit = softmax - onehot; also applies the SGD update to b_out in place.
__global__ void k_ce_grad(const float* __restrict__ logits, const int* __restrict__ y,
                          int ystride, int yoff, float* __restrict__ dlogit,
                          float* __restrict__ fw, const float* __restrict__ log_lr)
{
    int b = blockIdx.x, tid = threadIdx.x;
    __shared__ float red[128];
    float v = (tid < NCLS) ? logits[b * NCLS + tid] : -1e30f;
    red[tid] = v; __syncthreads();
    for (int s = 64; s > 0; s >>= 1) { if (tid < s) red[tid] = fmaxf(red[tid], red[tid + s]); __syncthreads(); }
    float m = red[0]; __syncthreads();
    float e = (tid < NCLS) ? expf(v - m) : 0.f;
    red[tid] = e; __syncthreads();
    for (int s = 64; s > 0; s >>= 1) { if (tid < s) red[tid] += red[tid + s]; __syncthreads(); }
    float sum = red[0];
    int label = y[b * ystride + yoff];
    if (tid < NCLS) {
        float dl = e / sum - (tid == label ? 1.f : 0.f);
        dlogit[b * NCLS + tid] = dl;
        fw[(long)b * PTOT + OFF_BO + tid] -= expf(*log_lr) * dl;
    }
}

// dz5[b,m] = (a5>0) ? gate * sum_n Wout[n,m]*dlogit[n] : 0  (reads pre-update W_out)
__global__ void k_head_bwd_f(const float* __restrict__ dlogit, const float* __restrict__ fw,
                             const float* __restrict__ a5, const float* __restrict__ gate, int gstride,
                             float* __restrict__ dz)
{
    int i = blockIdx.x * 256 + threadIdx.x;
    if (i >= NB * FEAT) return;
    int m = i % FEAT, b = i / FEAT;
    float acc = 0.f;
    const float* w  = fw + (long)b * PTOT + OFF_WO + m;
    const float* dl = dlogit + b * NCLS;
    for (int n = 0; n < NCLS; n++) acc = fmaf(w[(long)n * FEAT], dl[n], acc);
    acc *= gate[(long)b * gstride + m];
    dz[i] = (a5[i] > 0.f) ? acc : 0.f;
}

// W_out -= lr * dlogit ⊗ feat   (unique addresses, plain RMW)
__global__ void k_head_upd_w(const float* __restrict__ dlogit, const float* __restrict__ feat,
                             float* __restrict__ fw, const float* __restrict__ log_lr)
{
    int i = blockIdx.x * 256 + threadIdx.x;
    if (i >= NB * NCLS * FEAT) return;
    int m = i % FEAT; int t = i / FEAT;
    int cls = t % NCLS; int b = t / NCLS;
    fw[(long)b * PTOT + OFF_WO + (long)cls * FEAT + m] -=
        expf(*log_lr) * dlogit[b * NCLS + cls] * feat[(long)b * FEAT + m];
}

// bias_j -= lr * sum(dz) ; one warp per (b, oc)
__global__ void k_bwd_b_upd(const float* __restrict__ dz, float* __restrict__ fw,
                            const float* __restrict__ log_lr, int boff, int OC, int OHW)
{
    int gt = blockIdx.x * 256 + threadIdx.x;
    int warp = gt >> 5, lane = gt & 31;
    if (warp >= NB * OC) return;
    int oc = warp % OC, b = warp / OC;
    const float* p = dz + ((long)b * OC + oc) * OHW;
    float acc = 0.f;
    for (int i = lane; i < OHW; i += 32) acc += p[i];
#pragma unroll
    for (int o = 16; o; o >>= 1) acc += __shfl_down_sync(0xffffffffu, acc, o);
    if (!lane) fw[(long)b * PTOT + boff + oc] -= expf(*log_lr) * acc;
}

// W_j -= lr * dW via atomicAdd (fused SGD); thread owns (b, oc, ic, ky, oy-chunk)
template<int S>
__global__ void k_bwd_w_upd(const float* __restrict__ dz, const float* __restrict__ xin, long in_stride,
                            float* __restrict__ fw, const float* __restrict__ log_lr, int woff,
                            int IC, int OC, int IH, int IW, int OH, int OW, int NCH, int CH)
{
    int idx = blockIdx.x * 256 + threadIdx.x;
    if (idx >= NB * OC * IC * 3 * NCH) return;
    int c  = idx % NCH; int t = idx / NCH;
    int ky = t % 3;  t /= 3;
    int ic = t % IC; t /= IC;
    int oc = t % OC; int b = t / OC;
    const float* x = xin + (long)b * in_stride + (long)ic * IH * IW;
    const float* z = dz + ((long)b * OC + oc) * OH * OW;
    float a0 = 0.f, a1 = 0.f, a2 = 0.f;
    int oy0 = c * CH;
    for (int oy = oy0; oy < oy0 + CH; oy++) {
        int iy = oy * S + ky - 1;
        if ((unsigned)iy >= (unsigned)IH) continue;
        const float* xr = x + iy * IW;
        const float* zr = z + oy * OW;
        if (S == 1) {
            float w0 = 0.f, w1 = xr[0], w2;
            for (int ox = 0; ox < OW; ox++) {
                w2 = (ox + 1 < IW) ? xr[ox + 1] : 0.f;
                float zv = zr[ox];
                a0 = fmaf(zv, w0, a0); a1 = fmaf(zv, w1, a1); a2 = fmaf(zv, w2, a2);
                w0 = w1; w1 = w2;
            }
        } else {
            float carry = 0.f;
            for (int ox = 0; ox < OW; ox++) {
                float w0 = carry;
                float w1 = xr[2 * ox];
                float w2 = xr[2 * ox + 1];
                float zv = zr[ox];
                a0 = fmaf(zv, w0, a0); a1 = fmaf(zv, w1, a1); a2 = fmaf(zv, w2, a2);
                carry = w2;
            }
        }
    }
    float nlr = -expf(*log_lr);
    float* g = fw + (long)b * PTOT + woff + ((long)oc * IC + ic) * 9 + ky * 3;
    atomicAdd(g,     nlr * a0);
    atomicAdd(g + 1, nlr * a1);
    atomicAdd(g + 2, nlr * a2);
}

// OC-chunked bwd_x (stride-2): atomicAdd raw dx for 4 consecutive pixels.
__global__ void k_bwd_x_chunk(const float* __restrict__ dz, const float* __restrict__ fw, int woff,
                              float* __restrict__ raw,
                              int IC, int OC, int IH, int IW, int OH, int OW,
                              int NCHUNK, int OCH)
{
    int nix = IW >> 2;
    int base = NB * IC * IH * nix;
    int idx = blockIdx.x * 256 + threadIdx.x;
    if (idx >= base * NCHUNK) return;
    int ch = idx / base; int r = idx % base;
    int ix0 = (r % nix) * 4; int t = r / nix;
    int iy = t % IH; t /= IH;
    int ic = t % IC; int b = t / IC;
    long pix = (((long)b * IC + ic) * IH + iy) * IW + ix0;

    float acc0 = 0.f, acc1 = 0.f, acc2 = 0.f, acc3 = 0.f;
    int ox0p = ix0 >> 1;
    bool ok2 = (ox0p + 2 < OW), ok1 = (ox0p + 1 < OW);

    int oyv[3]; bool kyok[3];
#pragma unroll
    for (int ky = 0; ky < 3; ky++) {
        int ty = iy + 1 - ky;
        kyok[ky] = (ty >= 0) && !(ty & 1) && ((ty >> 1) < OH);
        oyv[ky] = ty >> 1;
    }
    const float* wb = fw + (long)b * PTOT + woff + (long)ic * 9;
    const float* zb = dz + (long)b * OC * OH * OW;
    int oc0 = ch * OCH;
    for (int oc = oc0; oc < oc0 + OCH; oc++) {
        const float* wp = wb + (long)oc * IC * 9;
        const float* zp = zb + (long)oc * OH * OW;
#pragma unroll
        for (int ky = 0; ky < 3; ky++) {
            if (!kyok[ky]) continue;
            const float* zr = zp + oyv[ky] * OW;
            float d0 = zr[ox0p];
            float d1 = ok1 ? zr[ox0p + 1] : 0.f;
            float d2 = ok2 ? zr[ox0p + 2] : 0.f;
            float wk0 = wp[ky * 3 + 0], wk1 = wp[ky * 3 + 1], wk2 = wp[ky * 3 + 2];
            acc0 = fmaf(wk1, d0, acc0);
            acc1 = fmaf(wk0, d1, fmaf(wk2, d0, acc1));
            acc2 = fmaf(wk1, d1, acc2);
            acc3 = fmaf(wk0, d2, fmaf(wk2, d1, acc3));
        }
    }
    atomicAdd(&raw[pix],     acc0);
    atomicAdd(&raw[pix + 1], acc1);
    atomicAdd(&raw[pix + 2], acc2);
    atomicAdd(&raw[pix + 3], acc3);
}

// dz = (act>0) ? raw : 0
__global__ void k_mask(const float* __restrict__ raw, const float* __restrict__ act,
                       float* __restrict__ dz, int count)
{
    int i = blockIdx.x * 256 + threadIdx.x;
    if (i < count) dz[i] = (act[i] > 0.f) ? raw[i] : 0.f;
}

__global__ void k_loss_eval(const float* __restrict__ logits, const int* __restrict__ y,
                            const float* __restrict__ log_lr, float* __restrict__ out)
{
    int e = blockIdx.x, tid = threadIdx.x;
    __shared__ float rv[128];
    __shared__ int   ri[128];
    float v = (tid < NCLS) ? logits[e * NCLS + tid] : -1e30f;
    rv[tid] = v; ri[tid] = tid; __syncthreads();
    for (int s = 64; s > 0; s >>= 1) {
        if (tid < s) {
            if (rv[tid + s] > rv[tid] || (rv[tid + s] == rv[tid] && ri[tid + s] < ri[tid])) {
                rv[tid] = rv[tid + s]; ri[tid] = ri[tid + s];
            }
        }
        __syncthreads();
    }
    float m = rv[0]; int amax = ri[0]; __syncthreads();
    float ex = (tid < NCLS) ? expf(v - m) : 0.f;
    rv[tid] = ex; __syncthreads();
    for (int s = 64; s > 0; s >>= 1) { if (tid < s) rv[tid] += rv[tid + s]; __syncthreads(); }
    if (tid == 0) {
        float lse = m + logf(rv[0]);
        int label = y[e];
        out[e]        = lse - logits[e * NCLS + label];
        out[129 + e]  = (amax == label) ? 1.f : 0.f;
        if (e == 0) out[128] = expf(*log_lr);
    }
}

// ---------------- launcher ----------------
struct LC { int ic, oc, ih, iw, oh, ow, s; };
static const LC lc[5] = {
    {  3,  32, 64, 64, 64, 64, 1},
    { 32,  64, 64, 64, 32, 32, 2},
    { 64, 128, 32, 32, 16, 16, 2},
    {128, 256, 16, 16,  8,  8, 2},
    {256, 256,  8,  8,  4,  4, 2},
};
static const int woffs[5] = {OFF_W0, OFF_W1, OFF_W2, OFF_W3, OFF_W4};
static const int boffs[5] = {OFF_B0, OFF_B1, OFF_B2, OFF_B3, OFF_B4};

static inline unsigned GRID(long n) { return (unsigned)((n + 255) / 256); }

extern "C" void kernel_launch(void* const* d_in, const int* in_sizes, int n_in,
                              void* d_out, int out_size)
{
    const float* pw[12];
    for (int i = 0; i < 12; i++) pw[i] = (const float*)d_in[i];
    const float* log_lr     = (const float*)d_in[12];
    const float* train_x    = (const float*)d_in[13];
    const float* test_x     = (const float*)d_in[14];
    const float* train_gate = (const float*)d_in[15];
    const float* test_gate  = (const float*)d_in[16];
    const int*   train_y    = (const int*)d_in[17];
    const int*   test_y     = (const int*)d_in[18];
    float* out = (float*)d_out;

    float *fw, *a1, *a2, *a3, *a4, *a5, *feat, *logit, *dlogit, *d1, *d2, *ta, *tb;
    cudaGetSymbolAddress((void**)&fw,     g_fw);
    cudaGetSymbolAddress((void**)&a1,     g_a1);
    cudaGetSymbolAddress((void**)&a2,     g_a2);
    cudaGetSymbolAddress((void**)&a3,     g_a3);
    cudaGetSymbolAddress((void**)&a4,     g_a4);
    cudaGetSymbolAddress((void**)&a5,     g_a5);
    cudaGetSymbolAddress((void**)&feat,   g_feat);
    cudaGetSymbolAddress((void**)&logit,  g_logit);
    cudaGetSymbolAddress((void**)&dlogit, g_dlogit);
    cudaGetSymbolAddress((void**)&d1,     g_d1);
    cudaGetSymbolAddress((void**)&d2,     g_d2);
    cudaGetSymbolAddress((void**)&ta,     g_ta);
    cudaGetSymbolAddress((void**)&tb,     g_tb);

    const int offs[12] = {OFF_W0, OFF_B0, OFF_W1, OFF_B1, OFF_W2, OFF_B2,
                          OFF_W3, OFF_B3, OFF_W4, OFF_B4, OFF_WO, OFF_BO};
    const int szs[12]  = {SZ_W0, SZ_B0, SZ_W1, SZ_B1, SZ_W2, SZ_B2,
                          SZ_W3, SZ_B3, SZ_W4, SZ_B4, SZ_WO, SZ_BO};
    for (int i = 0; i < 12; i++)
        k_bcast<<<GRID((long)NB * szs[i]), 256>>>(pw[i], fw, offs[i], szs[i]);

    float* acts[6] = {nullptr, a1, a2, a3, a4, a5};
    // IC-chunk counts for fwd (layers 2,3,4), OC-chunk counts for bwd_x
    const int fchunk[5] = {0, 0, 2, 4, 8};       // IC / 32
    const int xchunk[5] = {0, 2, 4, 8, 8};       // OC / 32
    const int wnch[5]   = {32, 4, 2, 1, 1};      // bwd_w oy-chunks

    // helper lambdas (host)
    auto fwd_direct_L0 = [&](const float* in, long instr, int wdiv, float* o, int N) {
        long tot = (long)N * (32 / 4) * 64 * (64 / 4);
        k_conv_fwd_t<1, 4, 4><<<GRID(tot), 256>>>(in, instr, fw, OFF_W0, OFF_B0, wdiv, o,
                                                  N, 3, 32, 64, 64, 64, 64);
    };
    auto fwd_direct_L1 = [&](const float* in, int wdiv, float* o, int N) {
        long tot = (long)N * (64 / 4) * 32 * (32 / 4);
        k_conv_fwd_t<2, 4, 4><<<GRID(tot), 256>>>(in, (long)32 * 64 * 64, fw, OFF_W1, OFF_B1, wdiv, o,
                                                  N, 32, 64, 64, 64, 32, 32);
    };
    auto fwd_chunked = [&](int j, const float* in, int wdiv, float* o, int N) {
        const LC& L = lc[j];
        long osz = (long)N * L.oc * L.oh * L.ow;
        cudaMemsetAsync(o, 0, osz * sizeof(float));
        int nch = fchunk[j];
        long instr = (long)L.ic * L.ih * L.iw;
        if (j == 2) {
            long tot = (long)N * (L.oc / 2) * L.oh * (L.ow / 4) * nch;
            k_conv_fwd_chunk<2, 2, 4><<<GRID(tot), 256>>>(in, instr, fw, woffs[j], wdiv, o,
                N, L.ic, L.oc, L.ih, L.iw, L.oh, L.ow, nch, L.ic / nch);
        } else if (j == 3) {
            long tot = (long)N * (L.oc / 2) * L.oh * (L.ow / 2) * nch;
            k_conv_fwd_chunk<2, 2, 2><<<GRID(tot), 256>>>(in, instr, fw, woffs[j], wdiv, o,
                N, L.ic, L.oc, L.ih, L.iw, L.oh, L.ow, nch, L.ic / nch);
        } else {
            long tot = (long)N * (L.oc / 2) * L.oh * L.ow * nch;
            k_conv_fwd_chunk<2, 2, 1><<<GRID(tot), 256>>>(in, instr, fw, woffs[j], wdiv, o,
                N, L.ic, L.oc, L.ih, L.iw, L.oh, L.ow, nch, L.ic / nch);
        }
        k_biasrelu<<<GRID(osz), 256>>>(o, fw, boffs[j], wdiv, N, L.oc, L.oh * L.ow);
    };

    // -------- inner loop --------
    for (int t = 0; t < NT; t++) {
        const float* in0 = train_x + (long)t * CHW;
        // forward
        fwd_direct_L0(in0, (long)NT * CHW, 1, a1, NB);
        fwd_direct_L1(a1, 1, a2, NB);
        fwd_chunked(2, a2, 1, a3, NB);
        fwd_chunked(3, a3, 1, a4, NB);
        fwd_chunked(4, a4, 1, a5, NB);
        k_gate<<<GRID((long)NB * FEAT), 256>>>(a5, train_gate + (long)t * FEAT, NT * FEAT, feat, NB);
        k_head_fwd<<<GRID((long)NB * NCLS * 32), 256>>>(feat, fw, 1, logit, NB);
        // backward (fused SGD)
        k_ce_grad<<<NB, 128>>>(logit, train_y, NT, t, dlogit, fw, log_lr);
        k_head_bwd_f<<<GRID((long)NB * FEAT), 256>>>(dlogit, fw, a5,
                                                     train_gate + (long)t * FEAT, NT * FEAT, d1);
        k_head_upd_w<<<GRID((long)NB * NCLS * FEAT), 256>>>(dlogit, feat, fw, log_lr);

        for (int j = 4; j >= 1; j--) {
            const LC& L = lc[j];
            long insz = (long)NB * L.ic * L.ih * L.iw;
            long instr = (long)L.ic * L.ih * L.iw;
            k_bwd_b_upd<<<GRID((long)NB * L.oc * 32), 256>>>(d1, fw, log_lr, boffs[j],
                                                             L.oc, L.oh * L.ow);
            cudaMemsetAsync(d2, 0, insz * sizeof(float));
            {
                int nch = xchunk[j];
                long tot = (long)NB * L.ic * L.ih * (L.iw / 4) * nch;
                k_bwd_x_chunk<<<GRID(tot), 256>>>(d1, fw, woffs[j], d2,
                    L.ic, L.oc, L.ih, L.iw, L.oh, L.ow, nch, L.oc / nch);
            }
            {
                int nch = wnch[j], chh = L.oh / wnch[j];
                long tot = (long)NB * L.oc * L.ic * 3 * nch;
                k_bwd_w_upd<2><<<GRID(tot), 256>>>(d1, acts[j], instr, fw, log_lr, woffs[j],
                    L.ic, L.oc, L.ih, L.iw, L.oh, L.ow, nch, chh);
            }
            k_mask<<<GRID(insz), 256>>>(d2, acts[j], d1, (int)insz);
        }
        k_bwd_b_upd<<<GRID((long)NB * 32 * 32), 256>>>(d1, fw, log_lr, OFF_B0, 32, 64 * 64);
        {
            int nch = wnch[0], chh = 64 / nch;
            long tot = (long)NB * 32 * 3 * 3 * nch;
            k_bwd_w_upd<1><<<GRID(tot), 256>>>(d1, in0, (long)NT * CHW, fw, log_lr, OFF_W0,
                3, 32, 64, 64, 64, 64, nch, chh);
        }
    }

    // -------- test forward --------
    fwd_direct_L0(test_x, (long)CHW, NL, ta, NTEST);
    fwd_direct_L1(ta, NL, tb, NTEST);
    fwd_chunked(2, tb, NL, ta, NTEST);
    fwd_chunked(3, ta, NL, tb, NTEST);
    fwd_chunked(4, tb, NL, ta, NTEST);
    k_gate<<<GRID((long)NTEST * FEAT), 256>>>(ta, test_gate, FEAT, tb, NTEST);
    k_head_fwd<<<GRID((long)NTEST * NCLS * 32), 256>>>(tb, fw, NL, out + 257, NTEST);
    k_loss_eval<<<NTEST, 128>>>(out + 257, test_y, log_lr, out);
}

// round 4
// speedup vs baseline: 1.6951x; 1.1678x over previous
#include <cuda_runtime.h>

// ---------------- problem constants ----------------
constexpr int NB    = 8;
constexpr int NT    = 5;
constexpr int NL    = 16;
constexpr int NTEST = NB * NL;          // 128
constexpr int NCLS  = 100;
constexpr int FEAT  = 4096;
constexpr int CHW   = 3 * 64 * 64;

constexpr int OFF_W0 = 0;        constexpr int SZ_W0 = 32 * 3 * 9;
constexpr int OFF_B0 = 864;      constexpr int SZ_B0 = 32;
constexpr int OFF_W1 = 896;      constexpr int SZ_W1 = 64 * 32 * 9;
constexpr int OFF_B1 = 19328;    constexpr int SZ_B1 = 64;
constexpr int OFF_W2 = 19392;    constexpr int SZ_W2 = 128 * 64 * 9;
constexpr int OFF_B2 = 93120;    constexpr int SZ_B2 = 128;
constexpr int OFF_W3 = 93248;    constexpr int SZ_W3 = 256 * 128 * 9;
constexpr int OFF_B3 = 388160;   constexpr int SZ_B3 = 256;
constexpr int OFF_W4 = 388416;   constexpr int SZ_W4 = 256 * 256 * 9;
constexpr int OFF_B4 = 978240;   constexpr int SZ_B4 = 256;
constexpr int OFF_WO = 978496;   constexpr int SZ_WO = NCLS * FEAT;
constexpr int OFF_BO = 1388096;  constexpr int SZ_BO = NCLS;
constexpr int PTOT   = 1388196;

// ---------------- static device scratch ----------------
__device__ float g_fw  [NB * PTOT];
__device__ float g_a1[NB * 131072];
__device__ float g_a2[NB * 65536];
__device__ float g_a3[NB * 32768];
__device__ float g_a4[NB * 16384];
__device__ float g_a5[NB * 4096];
__device__ float g_feat[NB * FEAT];
__device__ float g_logit[NB * NCLS];
__device__ float g_dlogit[NB * NCLS];
__device__ float g_d1[NB * 131072];   // dz (current layer grad-activation)
__device__ float g_d2[NB * 131072];   // raw accumulation buffer
__device__ float g_ta[NTEST * 131072];
__device__ float g_tb[NTEST * 131072];

// ---------------- kernels ----------------
__global__ void k_bcast(const float* __restrict__ src, float* __restrict__ fw, int off, int len)
{
    int i = blockIdx.x * 256 + threadIdx.x;
    if (i >= NB * len) return;
    int b = i / len, j = i % len;
    fw[(long)b * PTOT + off + j] = src[j];
}

// Direct tiled conv fwd with fused bias+relu.
template<int S, int TOC, int TOX>
__global__ void k_conv_fwd_t(const float* __restrict__ in, long in_stride,
                             const float* __restrict__ fw, int woff, int boff, int wdiv,
                             float* __restrict__ out,
                             int N, int IC, int OC, int IH, int IW, int OH, int OW)
{
    constexpr int XLEN = (TOX - 1) * S + 3;
    int idx = blockIdx.x * 256 + threadIdx.x;
    int nox = OW / TOX;
    int noc = OC / TOC;
    if (idx >= N * noc * OH * nox) return;
    int ox0 = (idx % nox) * TOX; int t = idx / nox;
    int oy  = t % OH;            t /= OH;
    int oc0 = (t % noc) * TOC;   int n = t / noc;
    long ex = n / wdiv;
    const float* wbase = fw + ex * PTOT + woff;
    const float* x     = in + (long)n * in_stride;

    float acc[TOC][TOX];
#pragma unroll
    for (int i = 0; i < TOC; i++) {
        float bv = fw[ex * PTOT + boff + oc0 + i];
#pragma unroll
        for (int j = 0; j < TOX; j++) acc[i][j] = bv;
    }
    int ixb = ox0 * S - 1;
    for (int ic = 0; ic < IC; ic++) {
        const float* xc = x + (long)ic * IH * IW;
#pragma unroll
        for (int ky = 0; ky < 3; ky++) {
            int iy = oy * S - 1 + ky;
            if ((unsigned)iy >= (unsigned)IH) continue;
            const float* xr = xc + iy * IW;
            float xv[XLEN];
#pragma unroll
            for (int u = 0; u < XLEN; u++) {
                int ix = ixb + u;
                xv[u] = ((unsigned)ix < (unsigned)IW) ? xr[ix] : 0.f;
            }
#pragma unroll
            for (int i = 0; i < TOC; i++) {
                const float* wp = wbase + ((long)(oc0 + i) * IC + ic) * 9 + ky * 3;
                float w0 = wp[0], w1 = wp[1], w2 = wp[2];
#pragma unroll
                for (int j = 0; j < TOX; j++)
                    acc[i][j] = fmaf(w0, xv[j * S],
                                fmaf(w1, xv[j * S + 1],
                                fmaf(w2, xv[j * S + 2], acc[i][j])));
            }
        }
    }
#pragma unroll
    for (int i = 0; i < TOC; i++) {
        float* op = out + (((long)n * OC + oc0 + i) * OH + oy) * OW + ox0;
#pragma unroll
        for (int j = 0; j < TOX; j++) op[j] = fmaxf(acc[i][j], 0.f);
    }
}

// IC-chunked conv fwd: atomic partial sums into zeroed out buffer.
template<int S, int TOC, int TOX>
__global__ void k_conv_fwd_chunk(const float* __restrict__ in, long in_stride,
                                 const float* __restrict__ fw, int woff, int wdiv,
                                 float* __restrict__ out,
                                 int N, int IC, int OC, int IH, int IW, int OH, int OW,
                                 int NCHUNK, int ICH)
{
    constexpr int XLEN = (TOX - 1) * S + 3;
    int nox = OW / TOX;
    int noc = OC / TOC;
    int base = N * noc * OH * nox;
    int idx = blockIdx.x * 256 + threadIdx.x;
    if (idx >= base * NCHUNK) return;
    int ch = idx / base; int r = idx % base;
    int ox0 = (r % nox) * TOX; int t = r / nox;
    int oy  = t % OH;          t /= OH;
    int oc0 = (t % noc) * TOC; int n = t / noc;
    long ex = n / wdiv;
    const float* wbase = fw + ex * PTOT + woff;
    const float* x     = in + (long)n * in_stride;

    float acc[TOC][TOX];
#pragma unroll
    for (int i = 0; i < TOC; i++)
#pragma unroll
        for (int j = 0; j < TOX; j++) acc[i][j] = 0.f;

    int ixb = ox0 * S - 1;
    int ic0 = ch * ICH;
    for (int ic = ic0; ic < ic0 + ICH; ic++) {
        const float* xc = x + (long)ic * IH * IW;
#pragma unroll
        for (int ky = 0; ky < 3; ky++) {
            int iy = oy * S - 1 + ky;
            if ((unsigned)iy >= (unsigned)IH) continue;
            const float* xr = xc + iy * IW;
            float xv[XLEN];
#pragma unroll
            for (int u = 0; u < XLEN; u++) {
                int ix = ixb + u;
                xv[u] = ((unsigned)ix < (unsigned)IW) ? xr[ix] : 0.f;
            }
#pragma unroll
            for (int i = 0; i < TOC; i++) {
                const float* wp = wbase + ((long)(oc0 + i) * IC + ic) * 9 + ky * 3;
                float w0 = wp[0], w1 = wp[1], w2 = wp[2];
#pragma unroll
                for (int j = 0; j < TOX; j++)
                    acc[i][j] = fmaf(w0, xv[j * S],
                                fmaf(w1, xv[j * S + 1],
                                fmaf(w2, xv[j * S + 2], acc[i][j])));
            }
        }
    }
#pragma unroll
    for (int i = 0; i < TOC; i++) {
        float* op = out + (((long)n * OC + oc0 + i) * OH + oy) * OW + ox0;
#pragma unroll
        for (int j = 0; j < TOX; j++) atomicAdd(op + j, acc[i][j]);
    }
}

// in-place: out = relu(out + bias[oc])
__global__ void k_biasrelu(float* __restrict__ out, const float* __restrict__ fw,
                           int boff, int wdiv, int N, int OC, int OHW)
{
    int i = blockIdx.x * 256 + threadIdx.x;
    if (i >= N * OC * OHW) return;
    int oc = (i / OHW) % OC;
    long ex = (i / (OC * OHW)) / wdiv;
    out[i] = fmaxf(out[i] + fw[ex * PTOT + boff + oc], 0.f);
}

__global__ void k_gate(const float* __restrict__ a, const float* __restrict__ gate, int gstride,
                       float* __restrict__ o, int N)
{
    int i = blockIdx.x * 256 + threadIdx.x;
    if (i >= N * FEAT) return;
    int n = i / FEAT, m = i % FEAT;
    o[i] = a[i] * gate[(long)n * gstride + m];
}

// logits[n,cls] = b_out[cls]
__global__ void k_logit_init(const float* __restrict__ fw, int wdiv, float* __restrict__ logits, int N)
{
    int i = blockIdx.x * 256 + threadIdx.x;
    if (i >= N * NCLS) return;
    int cls = i % NCLS;
    long ex = (i / NCLS) / wdiv;
    logits[i] = fw[ex * PTOT + OFF_BO + cls];
}

// FEAT-chunked head fwd: one warp per (n, cls, chunk of 1024); atomicAdd partial dot.
__global__ void k_head_fwd_chunk(const float* __restrict__ feat, const float* __restrict__ fw,
                                 int wdiv, float* __restrict__ logits, int N)
{
    int gt = blockIdx.x * 256 + threadIdx.x;
    int warp = gt >> 5, lane = gt & 31;
    if (warp >= N * NCLS * 4) return;
    int ch = warp & 3; int w2 = warp >> 2;
    int cls = w2 % NCLS, n = w2 / NCLS;
    long ex = n / wdiv;
    const float* w = fw + ex * PTOT + OFF_WO + (long)cls * FEAT + ch * 1024;
    const float* f = feat + (long)n * FEAT + ch * 1024;
    float acc = 0.f;
#pragma unroll 8
    for (int m = lane; m < 1024; m += 32) acc = fmaf(w[m], f[m], acc);
#pragma unroll
    for (int o = 16; o; o >>= 1) acc += __shfl_down_sync(0xffffffffu, acc, o);
    if (!lane) atomicAdd(&logits[w2], acc);
}

// dlogit = softmax - onehot; also updates b_out in place.
__global__ void k_ce_grad(const float* __restrict__ logits, const int* __restrict__ y,
                          int ystride, int yoff, float* __restrict__ dlogit,
                          float* __restrict__ fw, const float* __restrict__ log_lr)
{
    int b = blockIdx.x, tid = threadIdx.x;
    __shared__ float red[128];
    float v = (tid < NCLS) ? logits[b * NCLS + tid] : -1e30f;
    red[tid] = v; __syncthreads();
    for (int s = 64; s > 0; s >>= 1) { if (tid < s) red[tid] = fmaxf(red[tid], red[tid + s]); __syncthreads(); }
    float m = red[0]; __syncthreads();
    float e = (tid < NCLS) ? expf(v - m) : 0.f;
    red[tid] = e; __syncthreads();
    for (int s = 64; s > 0; s >>= 1) { if (tid < s) red[tid] += red[tid + s]; __syncthreads(); }
    float sum = red[0];
    int label = y[b * ystride + yoff];
    if (tid < NCLS) {
        float dl = e / sum - (tid == label ? 1.f : 0.f);
        dlogit[b * NCLS + tid] = dl;
        fw[(long)b * PTOT + OFF_BO + tid] -= expf(*log_lr) * dl;
    }
}

// NCLS-chunked head bwd to features: atomicAdd raw partial (no gate/mask yet).
__global__ void k_head_bwd_f_chunk(const float* __restrict__ dlogit, const float* __restrict__ fw,
                                   float* __restrict__ raw)
{
    int i = blockIdx.x * 256 + threadIdx.x;
    if (i >= NB * 4 * FEAT) return;
    int m = i % FEAT; int t = i / FEAT;
    int ch = t % 4; int b = t / 4;
    const float* w  = fw + (long)b * PTOT + OFF_WO + m + (long)(ch * 25) * FEAT;
    const float* dl = dlogit + b * NCLS + ch * 25;
    float acc = 0.f;
#pragma unroll
    for (int n = 0; n < 25; n++) acc = fmaf(w[(long)n * FEAT], dl[n], acc);
    atomicAdd(&raw[(long)b * FEAT + m], acc);
}

// dz = (a5>0) ? raw*gate : 0
__global__ void k_mask_gate(const float* __restrict__ raw, const float* __restrict__ a5,
                            const float* __restrict__ gate, int gstride, float* __restrict__ dz)
{
    int i = blockIdx.x * 256 + threadIdx.x;
    if (i >= NB * FEAT) return;
    int m = i % FEAT, b = i / FEAT;
    dz[i] = (a5[i] > 0.f) ? raw[i] * gate[(long)b * gstride + m] : 0.f;
}

// W_out -= lr * dlogit ⊗ feat
__global__ void k_head_upd_w(const float* __restrict__ dlogit, const float* __restrict__ feat,
                             float* __restrict__ fw, const float* __restrict__ log_lr)
{
    int i = blockIdx.x * 256 + threadIdx.x;
    if (i >= NB * NCLS * FEAT) return;
    int m = i % FEAT; int t = i / FEAT;
    int cls = t % NCLS; int b = t / NCLS;
    fw[(long)b * PTOT + OFF_WO + (long)cls * FEAT + m] -=
        expf(*log_lr) * dlogit[b * NCLS + cls] * feat[(long)b * FEAT + m];
}

// bias_j -= lr * sum(dz); one warp per (b, oc)
__global__ void k_bwd_b_upd(const float* __restrict__ dz, float* __restrict__ fw,
                            const float* __restrict__ log_lr, int boff, int OC, int OHW)
{
    int gt = blockIdx.x * 256 + threadIdx.x;
    int warp = gt >> 5, lane = gt & 31;
    if (warp >= NB * OC) return;
    int oc = warp % OC, b = warp / OC;
    const float* p = dz + ((long)b * OC + oc) * OHW;
    float acc = 0.f;
    for (int i = lane; i < OHW; i += 32) acc += p[i];
#pragma unroll
    for (int o = 16; o; o >>= 1) acc += __shfl_down_sync(0xffffffffu, acc, o);
    if (!lane) fw[(long)b * PTOT + boff + oc] -= expf(*log_lr) * acc;
}

// W_j -= lr * dW via atomicAdd; thread owns (b, oc, ic, ky, oy-chunk)
template<int S>
__global__ void k_bwd_w_upd(const float* __restrict__ dz, const float* __restrict__ xin, long in_stride,
                            float* __restrict__ fw, const float* __restrict__ log_lr, int woff,
                            int IC, int OC, int IH, int IW, int OH, int OW, int NCH, int CH)
{
    int idx = blockIdx.x * 256 + threadIdx.x;
    if (idx >= NB * OC * IC * 3 * NCH) return;
    int c  = idx % NCH; int t = idx / NCH;
    int ky = t % 3;  t /= 3;
    int ic = t % IC; t /= IC;
    int oc = t % OC; int b = t / OC;
    const float* x = xin + (long)b * in_stride + (long)ic * IH * IW;
    const float* z = dz + ((long)b * OC + oc) * OH * OW;
    float a0 = 0.f, a1 = 0.f, a2 = 0.f;
    int oy0 = c * CH;
    for (int oy = oy0; oy < oy0 + CH; oy++) {
        int iy = oy * S + ky - 1;
        if ((unsigned)iy >= (unsigned)IH) continue;
        const float* xr = x + iy * IW;
        const float* zr = z + oy * OW;
        if (S == 1) {
            float w0 = 0.f, w1 = xr[0], w2;
            for (int ox = 0; ox < OW; ox++) {
                w2 = (ox + 1 < IW) ? xr[ox + 1] : 0.f;
                float zv = zr[ox];
                a0 = fmaf(zv, w0, a0); a1 = fmaf(zv, w1, a1); a2 = fmaf(zv, w2, a2);
                w0 = w1; w1 = w2;
            }
        } else {
            float carry = 0.f;
            for (int ox = 0; ox < OW; ox++) {
                float w0 = carry;
                float w1 = xr[2 * ox];
                float w2 = xr[2 * ox + 1];
                float zv = zr[ox];
                a0 = fmaf(zv, w0, a0); a1 = fmaf(zv, w1, a1); a2 = fmaf(zv, w2, a2);
                carry = w2;
            }
        }
    }
    float nlr = -expf(*log_lr);
    float* g = fw + (long)b * PTOT + woff + ((long)oc * IC + ic) * 9 + ky * 3;
    atomicAdd(g,     nlr * a0);
    atomicAdd(g + 1, nlr * a1);
    atomicAdd(g + 2, nlr * a2);
}

// OC-chunked bwd_x (stride-2): atomicAdd raw dx for 4 consecutive pixels.
__global__ void k_bwd_x_chunk(const float* __restrict__ dz, const float* __restrict__ fw, int woff,
                              float* __restrict__ raw,
                              int IC, int OC, int IH, int IW, int OH, int OW,
                              int NCHUNK, int OCH)
{
    int nix = IW >> 2;
    int base = NB * IC * IH * nix;
    int idx = blockIdx.x * 256 + threadIdx.x;
    if (idx >= base * NCHUNK) return;
    int ch = idx / base; int r = idx % base;
    int ix0 = (r % nix) * 4; int t = r / nix;
    int iy = t % IH; t /= IH;
    int ic = t % IC; int b = t / IC;
    long pix = (((long)b * IC + ic) * IH + iy) * IW + ix0;

    float acc0 = 0.f, acc1 = 0.f, acc2 = 0.f, acc3 = 0.f;
    int ox0p = ix0 >> 1;
    bool ok2 = (ox0p + 2 < OW), ok1 = (ox0p + 1 < OW);

    int oyv[3]; bool kyok[3];
#pragma unroll
    for (int ky = 0; ky < 3; ky++) {
        int ty = iy + 1 - ky;
        kyok[ky] = (ty >= 0) && !(ty & 1) && ((ty >> 1) < OH);
        oyv[ky] = ty >> 1;
    }
    const float* wb = fw + (long)b * PTOT + woff + (long)ic * 9;
    const float* zb = dz + (long)b * OC * OH * OW;
    int oc0 = ch * OCH;
    for (int oc = oc0; oc < oc0 + OCH; oc++) {
        const float* wp = wb + (long)oc * IC * 9;
        const float* zp = zb + (long)oc * OH * OW;
#pragma unroll
        for (int ky = 0; ky < 3; ky++) {
            if (!kyok[ky]) continue;
            const float* zr = zp + oyv[ky] * OW;
            float d0 = zr[ox0p];
            float d1 = ok1 ? zr[ox0p + 1] : 0.f;
            float d2 = ok2 ? zr[ox0p + 2] : 0.f;
            float wk0 = wp[ky * 3 + 0], wk1 = wp[ky * 3 + 1], wk2 = wp[ky * 3 + 2];
            acc0 = fmaf(wk1, d0, acc0);
            acc1 = fmaf(wk0, d1, fmaf(wk2, d0, acc1));
            acc2 = fmaf(wk1, d1, acc2);
            acc3 = fmaf(wk0, d2, fmaf(wk2, d1, acc3));
        }
    }
    atomicAdd(&raw[pix],     acc0);
    atomicAdd(&raw[pix + 1], acc1);
    atomicAdd(&raw[pix + 2], acc2);
    atomicAdd(&raw[pix + 3], acc3);
}

// dz = (act>0) ? raw : 0
__global__ void k_mask(const float* __restrict__ raw, const float* __restrict__ act,
                       float* __restrict__ dz, int count)
{
    int i = blockIdx.x * 256 + threadIdx.x;
    if (i < count) dz[i] = (act[i] > 0.f) ? raw[i] : 0.f;
}

__global__ void k_loss_eval(const float* __restrict__ logits, const int* __restrict__ y,
                            const float* __restrict__ log_lr, float* __restrict__ out)
{
    int e = blockIdx.x, tid = threadIdx.x;
    __shared__ float rv[128];
    __shared__ int   ri[128];
    float v = (tid < NCLS) ? logits[e * NCLS + tid] : -1e30f;
    rv[tid] = v; ri[tid] = tid; __syncthreads();
    for (int s = 64; s > 0; s >>= 1) {
        if (tid < s) {
            if (rv[tid + s] > rv[tid] || (rv[tid + s] == rv[tid] && ri[tid + s] < ri[tid])) {
                rv[tid] = rv[tid + s]; ri[tid] = ri[tid + s];
            }
        }
        __syncthreads();
    }
    float m = rv[0]; int amax = ri[0]; __syncthreads();
    float ex = (tid < NCLS) ? expf(v - m) : 0.f;
    rv[tid] = ex; __syncthreads();
    for (int s = 64; s > 0; s >>= 1) { if (tid < s) rv[tid] += rv[tid + s]; __syncthreads(); }
    if (tid == 0) {
        float lse = m + logf(rv[0]);
        int label = y[e];
        out[e]        = lse - logits[e * NCLS + label];
        out[129 + e]  = (amax == label) ? 1.f : 0.f;
        if (e == 0) out[128] = expf(*log_lr);
    }
}

// ---------------- launcher ----------------
struct LC { int ic, oc, ih, iw, oh, ow, s; };
static const LC lc[5] = {
    {  3,  32, 64, 64, 64, 64, 1},
    { 32,  64, 64, 64, 32, 32, 2},
    { 64, 128, 32, 32, 16, 16, 2},
    {128, 256, 16, 16,  8,  8, 2},
    {256, 256,  8,  8,  4,  4, 2},
};
static const int woffs[5] = {OFF_W0, OFF_W1, OFF_W2, OFF_W3, OFF_W4};
static const int boffs[5] = {OFF_B0, OFF_B1, OFF_B2, OFF_B3, OFF_B4};

static inline unsigned GRID(long n) { return (unsigned)((n + 255) / 256); }

extern "C" void kernel_launch(void* const* d_in, const int* in_sizes, int n_in,
                              void* d_out, int out_size)
{
    const float* pw[12];
    for (int i = 0; i < 12; i++) pw[i] = (const float*)d_in[i];
    const float* log_lr     = (const float*)d_in[12];
    const float* train_x    = (const float*)d_in[13];
    const float* test_x     = (const float*)d_in[14];
    const float* train_gate = (const float*)d_in[15];
    const float* test_gate  = (const float*)d_in[16];
    const int*   train_y    = (const int*)d_in[17];
    const int*   test_y     = (const int*)d_in[18];
    float* out = (float*)d_out;

    float *fw, *a1, *a2, *a3, *a4, *a5, *feat, *logit, *dlogit, *d1, *d2, *ta, *tb;
    cudaGetSymbolAddress((void**)&fw,     g_fw);
    cudaGetSymbolAddress((void**)&a1,     g_a1);
    cudaGetSymbolAddress((void**)&a2,     g_a2);
    cudaGetSymbolAddress((void**)&a3,     g_a3);
    cudaGetSymbolAddress((void**)&a4,     g_a4);
    cudaGetSymbolAddress((void**)&a5,     g_a5);
    cudaGetSymbolAddress((void**)&feat,   g_feat);
    cudaGetSymbolAddress((void**)&logit,  g_logit);
    cudaGetSymbolAddress((void**)&dlogit, g_dlogit);
    cudaGetSymbolAddress((void**)&d1,     g_d1);
    cudaGetSymbolAddress((void**)&d2,     g_d2);
    cudaGetSymbolAddress((void**)&ta,     g_ta);
    cudaGetSymbolAddress((void**)&tb,     g_tb);

    const int offs[12] = {OFF_W0, OFF_B0, OFF_W1, OFF_B1, OFF_W2, OFF_B2,
                          OFF_W3, OFF_B3, OFF_W4, OFF_B4, OFF_WO, OFF_BO};
    const int szs[12]  = {SZ_W0, SZ_B0, SZ_W1, SZ_B1, SZ_W2, SZ_B2,
                          SZ_W3, SZ_B3, SZ_W4, SZ_B4, SZ_WO, SZ_BO};
    for (int i = 0; i < 12; i++)
        k_bcast<<<GRID((long)NB * szs[i]), 256>>>(pw[i], fw, offs[i], szs[i]);

    float* acts[6] = {nullptr, a1, a2, a3, a4, a5};

    // inner fwd: IC chunk sizes per layer (layers 1..4)
    const int f_ich[5] = {0, 8, 8, 8, 4};
    // bwd_x: OC chunk size 8 for all layers
    // bwd_w: oy chunks per layer
    const int wnch[5] = {32, 8, 4, 2, 1};

    // inner chunked fwd (TOC=4, TOX=4)
    auto fwd_inner = [&](int j, const float* in, float* o) {
        const LC& L = lc[j];
        long osz = (long)NB * L.oc * L.oh * L.ow;
        cudaMemsetAsync(o, 0, osz * sizeof(float));
        int ich = f_ich[j], nch = L.ic / ich;
        long instr = (long)L.ic * L.ih * L.iw;
        long tot = (long)NB * (L.oc / 4) * L.oh * (L.ow / 4) * nch;
        k_conv_fwd_chunk<2, 4, 4><<<GRID(tot), 256>>>(in, instr, fw, woffs[j], 1, o,
            NB, L.ic, L.oc, L.ih, L.iw, L.oh, L.ow, nch, ich);
        k_biasrelu<<<GRID(osz), 256>>>(o, fw, boffs[j], 1, NB, L.oc, L.oh * L.ow);
    };
    // test chunked fwd (TOC=8, TOX=4), ICH=32
    auto fwd_test = [&](int j, const float* in, float* o) {
        const LC& L = lc[j];
        long osz = (long)NTEST * L.oc * L.oh * L.ow;
        cudaMemsetAsync(o, 0, osz * sizeof(float));
        int ich = 32, nch = L.ic / ich;
        long instr = (long)L.ic * L.ih * L.iw;
        long tot = (long)NTEST * (L.oc / 8) * L.oh * (L.ow / 4) * nch;
        k_conv_fwd_chunk<2, 8, 4><<<GRID(tot), 256>>>(in, instr, fw, woffs[j], NL, o,
            NTEST, L.ic, L.oc, L.ih, L.iw, L.oh, L.ow, nch, ich);
        k_biasrelu<<<GRID(osz), 256>>>(o, fw, boffs[j], NL, NTEST, L.oc, L.oh * L.ow);
    };

    // -------- inner loop --------
    for (int t = 0; t < NT; t++) {
        const float* in0 = train_x + (long)t * CHW;
        // forward
        {
            long tot = (long)NB * (32 / 4) * 64 * (64 / 4);
            k_conv_fwd_t<1, 4, 4><<<GRID(tot), 256>>>(in0, (long)NT * CHW, fw, OFF_W0, OFF_B0, 1, a1,
                                                      NB, 3, 32, 64, 64, 64, 64);
        }
        fwd_inner(1, a1, a2);
        fwd_inner(2, a2, a3);
        fwd_inner(3, a3, a4);
        fwd_inner(4, a4, a5);
        k_gate<<<GRID((long)NB * FEAT), 256>>>(a5, train_gate + (long)t * FEAT, NT * FEAT, feat, NB);
        k_logit_init<<<GRID((long)NB * NCLS), 256>>>(fw, 1, logit, NB);
        k_head_fwd_chunk<<<GRID((long)NB * NCLS * 4 * 32), 256>>>(feat, fw, 1, logit, NB);
        // backward (fused SGD)
        k_ce_grad<<<NB, 128>>>(logit, train_y, NT, t, dlogit, fw, log_lr);
        cudaMemsetAsync(d2, 0, (long)NB * FEAT * sizeof(float));
        k_head_bwd_f_chunk<<<GRID((long)NB * 4 * FEAT), 256>>>(dlogit, fw, d2);
        k_mask_gate<<<GRID((long)NB * FEAT), 256>>>(d2, a5, train_gate + (long)t * FEAT, NT * FEAT, d1);
        k_head_upd_w<<<GRID((long)NB * NCLS * FEAT), 256>>>(dlogit, feat, fw, log_lr);

        for (int j = 4; j >= 1; j--) {
            const LC& L = lc[j];
            long insz = (long)NB * L.ic * L.ih * L.iw;
            long instr = (long)L.ic * L.ih * L.iw;
            k_bwd_b_upd<<<GRID((long)NB * L.oc * 32), 256>>>(d1, fw, log_lr, boffs[j],
                                                             L.oc, L.oh * L.ow);
            cudaMemsetAsync(d2, 0, insz * sizeof(float));
            {
                int nch = L.oc / 8;
                long tot = (long)NB * L.ic * L.ih * (L.iw / 4) * nch;
                k_bwd_x_chunk<<<GRID(tot), 256>>>(d1, fw, woffs[j], d2,
                    L.ic, L.oc, L.ih, L.iw, L.oh, L.ow, nch, 8);
            }
            {
                int nch = wnch[j], chh = L.oh / nch;
                long tot = (long)NB * L.oc * L.ic * 3 * nch;
                k_bwd_w_upd<2><<<GRID(tot), 256>>>(d1, acts[j], instr, fw, log_lr, woffs[j],
                    L.ic, L.oc, L.ih, L.iw, L.oh, L.ow, nch, chh);
            }
            k_mask<<<GRID(insz), 256>>>(d2, acts[j], d1, (int)insz);
        }
        k_bwd_b_upd<<<GRID((long)NB * 32 * 32), 256>>>(d1, fw, log_lr, OFF_B0, 32, 64 * 64);
        {
            int nch = wnch[0], chh = 64 / nch;
            long tot = (long)NB * 32 * 3 * 3 * nch;
            k_bwd_w_upd<1><<<GRID(tot), 256>>>(d1, in0, (long)NT * CHW, fw, log_lr, OFF_W0,
                3, 32, 64, 64, 64, 64, nch, chh);
        }
    }

    // -------- test forward --------
    {
        long tot = (long)NTEST * (32 / 4) * 64 * (64 / 4);
        k_conv_fwd_t<1, 4, 4><<<GRID(tot), 256>>>(test_x, (long)CHW, fw, OFF_W0, OFF_B0, NL, ta,
                                                  NTEST, 3, 32, 64, 64, 64, 64);
    }
    {   // L1 direct (IC=32 fits one pass), TOC=8 TOX=4
        long tot = (long)NTEST * (64 / 8) * 32 * (32 / 4);
        k_conv_fwd_t<2, 8, 4><<<GRID(tot), 256>>>(ta, (long)32 * 64 * 64, fw, OFF_W1, OFF_B1, NL, tb,
                                                  NTEST, 32, 64, 64, 64, 32, 32);
    }
    fwd_test(2, tb, ta);
    fwd_test(3, ta, tb);
    fwd_test(4, tb, ta);
    k_gate<<<GRID((long)NTEST * FEAT), 256>>>(ta, test_gate, FEAT, tb, NTEST);
    k_logit_init<<<GRID((long)NTEST * NCLS), 256>>>(fw, NL, out + 257, NTEST);
    k_head_fwd_chunk<<<GRID((long)NTEST * NCLS * 4 * 32), 256>>>(tb, fw, NL, out + 257, NTEST);
    k_loss_eval<<<NTEST, 128>>>(out + 257, test_y, log_lr, out);
}